// round 4
// baseline (speedup 1.0000x reference)
#include <cuda_runtime.h>
#include <cstdint>

// Problem dims (fixed by the benchmark's setup_inputs)
#define T_TOK 8192
#define H_DIM 2048
#define I_DIM 4096
#define E_NUM 8

#define SWIGLU_ALPHA 1.702f
#define SWIGLU_LIMIT 7.0f

// 134 MB activation scratch (static __device__ — no allocation in kernel_launch)
__device__ __align__(128) float g_act[(size_t)T_TOK * (size_t)I_DIM];

// ---------------------------------------------------------------------------
// helpers
// ---------------------------------------------------------------------------
__device__ __forceinline__ unsigned f2tf32(float f) {
    unsigned u;
    asm volatile("cvt.rna.tf32.f32 %0, %1;" : "=r"(u) : "f"(f));
    return u;
}

__device__ __forceinline__ void mma_tf32(float c[4],
                                         unsigned a0, unsigned a1, unsigned a2, unsigned a3,
                                         unsigned b0, unsigned b1) {
    asm volatile(
        "mma.sync.aligned.m16n8k8.row.col.f32.tf32.tf32.f32 "
        "{%0,%1,%2,%3}, {%4,%5,%6,%7}, {%8,%9}, {%0,%1,%2,%3};\n"
        : "+f"(c[0]), "+f"(c[1]), "+f"(c[2]), "+f"(c[3])
        : "r"(a0), "r"(a1), "r"(a2), "r"(a3), "r"(b0), "r"(b1));
}

__device__ __forceinline__ void cp_async16(uint32_t smem_addr, const void* gmem) {
    asm volatile("cp.async.cg.shared.global [%0], [%1], 16;\n" :: "r"(smem_addr), "l"(gmem));
}
__device__ __forceinline__ void cp_commit() { asm volatile("cp.async.commit_group;\n"); }
template <int N>
__device__ __forceinline__ void cp_wait() { asm volatile("cp.async.wait_group %0;\n" :: "n"(N)); }

__device__ __forceinline__ float swiglu_act(float gt, float u) {
    gt = fminf(gt, SWIGLU_LIMIT);
    u  = fminf(fmaxf(u, -SWIGLU_LIMIT), SWIGLU_LIMIT);
    float sig = 1.0f / (1.0f + __expf(-SWIGLU_ALPHA * gt));
    return (u + 1.0f) * (gt * sig);
}

// ---------------------------------------------------------------------------
// Kernel 1: fused gate+up GEMM + bias + SwiGLU -> g_act
// Tile: BM=128, BN=128, BK=32. 256 threads = 8 warps (2 x 4), warp tile 64x32.
// ---------------------------------------------------------------------------
#define BM 128
#define BK 32
#define BN1 128
#define LDA 36            // A smem stride (floats): bank = (4m + k) % 32, conflict-free
#define LDB1 136          // B smem stride (floats): bank = (8k + n) % 32, conflict-free
#define A_FLOATS (BM * LDA)                 // 4608
#define B1_FLOATS (BK * LDB1)               // 4352
#define BUF1 (A_FLOATS + 2 * B1_FLOATS)     // 13312 floats per buffer
#define SMEM1_BYTES (2 * BUF1 * 4)          // 106496 B

extern "C" __global__ void __launch_bounds__(256, 1)
fused_gate_up_kernel(const float* __restrict__ x,
                     const int*   __restrict__ offs,
                     const float* __restrict__ gate_w,
                     const float* __restrict__ up_w,
                     const float* __restrict__ gate_b,
                     const float* __restrict__ up_b)
{
    extern __shared__ float smem[];
    const int tid = threadIdx.x;
    const int wid = tid >> 5, lane = tid & 31;
    const int g = lane >> 2, tg = lane & 3;       // groupID, threadID-in-group
    const int warp_m = wid >> 2, warp_n = wid & 3;
    const int m0 = blockIdx.y * BM;
    const int n0 = blockIdx.x * BN1;

    // expert for this row block (offsets are cumulative end offsets)
    int e = 0;
    while (e < E_NUM - 1 && __ldg(&offs[e]) <= m0) ++e;

    const float* Wg = gate_w + (size_t)e * H_DIM * I_DIM;
    const float* Wu = up_w   + (size_t)e * H_DIM * I_DIM;

    float accG[4][4][4];
    float accU[4][4][4];
#pragma unroll
    for (int i = 0; i < 4; i++)
#pragma unroll
        for (int j = 0; j < 4; j++)
#pragma unroll
            for (int k = 0; k < 4; k++) { accG[i][j][k] = 0.f; accU[i][j][k] = 0.f; }

    const uint32_t smem_u = (uint32_t)__cvta_generic_to_shared(smem);

    auto load_tile = [&](int kt, int buf) {
        const int k0 = kt * BK;
        const uint32_t base = smem_u + (uint32_t)buf * (BUF1 * 4);
        // A: 128x32 floats = 1024 float4, 4 per thread
#pragma unroll
        for (int i = 0; i < 4; i++) {
            int idx = tid + i * 256;
            int row = idx >> 3, kc = idx & 7;
            cp_async16(base + (uint32_t)(row * LDA + kc * 4) * 4,
                       x + (size_t)(m0 + row) * H_DIM + k0 + kc * 4);
        }
        // Bg, Bu: each 32x128 floats = 1024 float4, 4 per thread each
#pragma unroll
        for (int i = 0; i < 4; i++) {
            int idx = tid + i * 256;
            int kr = idx >> 5, nc = idx & 31;
            size_t goff = (size_t)(k0 + kr) * I_DIM + n0 + nc * 4;
            cp_async16(base + (uint32_t)(A_FLOATS + kr * LDB1 + nc * 4) * 4, Wg + goff);
            cp_async16(base + (uint32_t)(A_FLOATS + B1_FLOATS + kr * LDB1 + nc * 4) * 4, Wu + goff);
        }
        cp_commit();
    };

    load_tile(0, 0);
    const int KT = H_DIM / BK;
    for (int kt = 0; kt < KT; ++kt) {
        const int cur = kt & 1;
        if (kt + 1 < KT) { load_tile(kt + 1, cur ^ 1); cp_wait<1>(); }
        else             { cp_wait<0>(); }
        __syncthreads();

        const float* As = smem + cur * BUF1;
        const float* Bg = As + A_FLOATS;
        const float* Bu = Bg + B1_FLOATS;

#pragma unroll
        for (int kk = 0; kk < 4; ++kk) {
            const int k8 = kk * 8;
            unsigned a[4][4];
#pragma unroll
            for (int mt = 0; mt < 4; ++mt) {
                int r = warp_m * 64 + mt * 16 + g;
                a[mt][0] = f2tf32(As[r * LDA + k8 + tg]);
                a[mt][1] = f2tf32(As[(r + 8) * LDA + k8 + tg]);
                a[mt][2] = f2tf32(As[r * LDA + k8 + tg + 4]);
                a[mt][3] = f2tf32(As[(r + 8) * LDA + k8 + tg + 4]);
            }
            unsigned bg[4][2], bu[4][2];
#pragma unroll
            for (int nt = 0; nt < 4; ++nt) {
                int c = warp_n * 32 + nt * 8 + g;
                bg[nt][0] = f2tf32(Bg[(k8 + tg) * LDB1 + c]);
                bg[nt][1] = f2tf32(Bg[(k8 + tg + 4) * LDB1 + c]);
                bu[nt][0] = f2tf32(Bu[(k8 + tg) * LDB1 + c]);
                bu[nt][1] = f2tf32(Bu[(k8 + tg + 4) * LDB1 + c]);
            }
#pragma unroll
            for (int mt = 0; mt < 4; ++mt)
#pragma unroll
                for (int nt = 0; nt < 4; ++nt) {
                    mma_tf32(accG[mt][nt], a[mt][0], a[mt][1], a[mt][2], a[mt][3], bg[nt][0], bg[nt][1]);
                    mma_tf32(accU[mt][nt], a[mt][0], a[mt][1], a[mt][2], a[mt][3], bu[nt][0], bu[nt][1]);
                }
        }
        __syncthreads();
    }

    // epilogue: bias + SwiGLU -> g_act (fp32, row-major T x I)
    const float* gb = gate_b + (size_t)e * I_DIM;
    const float* ub = up_b   + (size_t)e * I_DIM;
#pragma unroll
    for (int mt = 0; mt < 4; ++mt) {
        int r0 = m0 + warp_m * 64 + mt * 16 + g;
#pragma unroll
        for (int nt = 0; nt < 4; ++nt) {
            int c = n0 + warp_n * 32 + nt * 8 + tg * 2;
            float gb0 = gb[c], gb1 = gb[c + 1];
            float ub0 = ub[c], ub1 = ub[c + 1];
            float2 v0, v1;
            v0.x = swiglu_act(accG[mt][nt][0] + gb0, accU[mt][nt][0] + ub0);
            v0.y = swiglu_act(accG[mt][nt][1] + gb1, accU[mt][nt][1] + ub1);
            v1.x = swiglu_act(accG[mt][nt][2] + gb0, accU[mt][nt][2] + ub0);
            v1.y = swiglu_act(accG[mt][nt][3] + gb1, accU[mt][nt][3] + ub1);
            *reinterpret_cast<float2*>(&g_act[(size_t)r0 * I_DIM + c])        = v0;
            *reinterpret_cast<float2*>(&g_act[(size_t)(r0 + 8) * I_DIM + c])  = v1;
        }
    }
}

// ---------------------------------------------------------------------------
// Kernel 2: down GEMM (g_act @ down_w + down_b) -> out
// Tile: BM=128, BN=256, BK=32. 8 warps (2 x 4), warp tile 64x64.
// ---------------------------------------------------------------------------
#define BN2 256
#define LDB2 264          // bank = (8k + n) % 32, conflict-free
#define B2_FLOATS (BK * LDB2)               // 8448
#define BUF2 (A_FLOATS + B2_FLOATS)         // 13056 floats
#define SMEM2_BYTES (2 * BUF2 * 4)          // 104448 B

extern "C" __global__ void __launch_bounds__(256, 1)
down_kernel(const int*   __restrict__ offs,
            const float* __restrict__ down_w,
            const float* __restrict__ down_b,
            float*       __restrict__ out)
{
    extern __shared__ float smem[];
    const int tid = threadIdx.x;
    const int wid = tid >> 5, lane = tid & 31;
    const int g = lane >> 2, tg = lane & 3;
    const int warp_m = wid >> 2, warp_n = wid & 3;
    const int m0 = blockIdx.y * BM;
    const int n0 = blockIdx.x * BN2;

    int e = 0;
    while (e < E_NUM - 1 && __ldg(&offs[e]) <= m0) ++e;

    const float* A  = g_act;
    const float* Wd = down_w + (size_t)e * I_DIM * H_DIM;

    float acc[4][8][4];
#pragma unroll
    for (int i = 0; i < 4; i++)
#pragma unroll
        for (int j = 0; j < 8; j++)
#pragma unroll
            for (int k = 0; k < 4; k++) acc[i][j][k] = 0.f;

    const uint32_t smem_u = (uint32_t)__cvta_generic_to_shared(smem);

    auto load_tile = [&](int kt, int buf) {
        const int k0 = kt * BK;
        const uint32_t base = smem_u + (uint32_t)buf * (BUF2 * 4);
#pragma unroll
        for (int i = 0; i < 4; i++) {
            int idx = tid + i * 256;
            int row = idx >> 3, kc = idx & 7;
            cp_async16(base + (uint32_t)(row * LDA + kc * 4) * 4,
                       A + (size_t)(m0 + row) * I_DIM + k0 + kc * 4);
        }
        // B: 32 x 256 floats = 2048 float4, 8 per thread
#pragma unroll
        for (int i = 0; i < 8; i++) {
            int idx = tid + i * 256;
            int kr = idx >> 6, nc = idx & 63;
            cp_async16(base + (uint32_t)(A_FLOATS + kr * LDB2 + nc * 4) * 4,
                       Wd + (size_t)(k0 + kr) * H_DIM + n0 + nc * 4);
        }
        cp_commit();
    };

    load_tile(0, 0);
    const int KT = I_DIM / BK;
    for (int kt = 0; kt < KT; ++kt) {
        const int cur = kt & 1;
        if (kt + 1 < KT) { load_tile(kt + 1, cur ^ 1); cp_wait<1>(); }
        else             { cp_wait<0>(); }
        __syncthreads();

        const float* As = smem + cur * BUF2;
        const float* Bs = As + A_FLOATS;

#pragma unroll
        for (int kk = 0; kk < 4; ++kk) {
            const int k8 = kk * 8;
            unsigned a[4][4];
#pragma unroll
            for (int mt = 0; mt < 4; ++mt) {
                int r = warp_m * 64 + mt * 16 + g;
                a[mt][0] = f2tf32(As[r * LDA + k8 + tg]);
                a[mt][1] = f2tf32(As[(r + 8) * LDA + k8 + tg]);
                a[mt][2] = f2tf32(As[r * LDA + k8 + tg + 4]);
                a[mt][3] = f2tf32(As[(r + 8) * LDA + k8 + tg + 4]);
            }
            unsigned b[8][2];
#pragma unroll
            for (int nt = 0; nt < 8; ++nt) {
                int c = warp_n * 64 + nt * 8 + g;
                b[nt][0] = f2tf32(Bs[(k8 + tg) * LDB2 + c]);
                b[nt][1] = f2tf32(Bs[(k8 + tg + 4) * LDB2 + c]);
            }
#pragma unroll
            for (int mt = 0; mt < 4; ++mt)
#pragma unroll
                for (int nt = 0; nt < 8; ++nt)
                    mma_tf32(acc[mt][nt], a[mt][0], a[mt][1], a[mt][2], a[mt][3], b[nt][0], b[nt][1]);
        }
        __syncthreads();
    }

    const float* db = down_b + (size_t)e * H_DIM;
#pragma unroll
    for (int mt = 0; mt < 4; ++mt) {
        int r0 = m0 + warp_m * 64 + mt * 16 + g;
#pragma unroll
        for (int nt = 0; nt < 8; ++nt) {
            int c = n0 + warp_n * 64 + nt * 8 + tg * 2;
            float b0 = db[c], b1 = db[c + 1];
            float2 v0, v1;
            v0.x = acc[mt][nt][0] + b0;
            v0.y = acc[mt][nt][1] + b1;
            v1.x = acc[mt][nt][2] + b0;
            v1.y = acc[mt][nt][3] + b1;
            *reinterpret_cast<float2*>(&out[(size_t)r0 * H_DIM + c])       = v0;
            *reinterpret_cast<float2*>(&out[(size_t)(r0 + 8) * H_DIM + c]) = v1;
        }
    }
}

// ---------------------------------------------------------------------------
// launch
// ---------------------------------------------------------------------------
extern "C" void kernel_launch(void* const* d_in, const int* in_sizes, int n_in,
                              void* d_out, int out_size)
{
    const float* x      = (const float*)d_in[0];
    const int*   offs   = (const int*)  d_in[1];
    const float* gate_w = (const float*)d_in[2];
    const float* up_w   = (const float*)d_in[3];
    const float* down_w = (const float*)d_in[4];
    const float* gate_b = (const float*)d_in[5];
    const float* up_b   = (const float*)d_in[6];
    const float* down_b = (const float*)d_in[7];
    float* out = (float*)d_out;

    cudaFuncSetAttribute(fused_gate_up_kernel,
                         cudaFuncAttributeMaxDynamicSharedMemorySize, SMEM1_BYTES);
    cudaFuncSetAttribute(down_kernel,
                         cudaFuncAttributeMaxDynamicSharedMemorySize, SMEM2_BYTES);

    dim3 grid1(I_DIM / BN1, T_TOK / BM);   // (32, 64)
    fused_gate_up_kernel<<<grid1, 256, SMEM1_BYTES>>>(x, offs, gate_w, up_w, gate_b, up_b);

    dim3 grid2(H_DIM / BN2, T_TOK / BM);   // (8, 64)
    down_kernel<<<grid2, 256, SMEM2_BYTES>>>(offs, down_w, down_b, out);
}

// round 7
// speedup vs baseline: 1.5817x; 1.5817x over previous
#include <cuda_runtime.h>
#include <cuda_fp16.h>
#include <cstdint>

#define T_TOK 8192
#define H_DIM 2048
#define I_DIM 4096
#define E_NUM 8
#define SWIGLU_ALPHA 1.702f
#define SWIGLU_LIMIT 7.0f

// Static device scratch (no allocations allowed anywhere).
// fp16 copies of inputs + fp16 intermediate activations.
__device__ __align__(128) __half g_xh [(size_t)T_TOK * H_DIM];
__device__ __align__(128) __half g_gwh[(size_t)E_NUM * H_DIM * I_DIM];
__device__ __align__(128) __half g_uwh[(size_t)E_NUM * H_DIM * I_DIM];
__device__ __align__(128) __half g_dwh[(size_t)E_NUM * I_DIM * H_DIM];
__device__ __align__(128) __half g_act[(size_t)T_TOK * I_DIM];

// ---------------------------------------------------------------------------
// helpers
// ---------------------------------------------------------------------------
__device__ __forceinline__ uint32_t smem_u32(const void* p) {
    uint32_t a;
    asm("{ .reg .u64 t; cvta.to.shared.u64 t, %1; cvt.u32.u64 %0, t; }" : "=r"(a) : "l"(p));
    return a;
}
__device__ __forceinline__ void cp_async16(uint32_t saddr, const void* g) {
    asm volatile("cp.async.cg.shared.global [%0], [%1], 16;\n" :: "r"(saddr), "l"(g));
}
__device__ __forceinline__ void cp_commit() { asm volatile("cp.async.commit_group;\n"); }
template <int N> __device__ __forceinline__ void cp_wait() {
    asm volatile("cp.async.wait_group %0;\n" :: "n"(N));
}
__device__ __forceinline__ void ldsm4(uint32_t r[4], uint32_t addr) {
    asm volatile("ldmatrix.sync.aligned.m8n8.x4.shared.b16 {%0,%1,%2,%3}, [%4];"
                 : "=r"(r[0]), "=r"(r[1]), "=r"(r[2]), "=r"(r[3]) : "r"(addr));
}
__device__ __forceinline__ void ldsm4t(uint32_t r[4], uint32_t addr) {
    asm volatile("ldmatrix.sync.aligned.m8n8.x4.trans.shared.b16 {%0,%1,%2,%3}, [%4];"
                 : "=r"(r[0]), "=r"(r[1]), "=r"(r[2]), "=r"(r[3]) : "r"(addr));
}
__device__ __forceinline__ void mma_f16(float c[4], const uint32_t a[4],
                                        uint32_t b0, uint32_t b1) {
    asm volatile(
        "mma.sync.aligned.m16n8k16.row.col.f32.f16.f16.f32 "
        "{%0,%1,%2,%3}, {%4,%5,%6,%7}, {%8,%9}, {%0,%1,%2,%3};\n"
        : "+f"(c[0]), "+f"(c[1]), "+f"(c[2]), "+f"(c[3])
        : "r"(a[0]), "r"(a[1]), "r"(a[2]), "r"(a[3]), "r"(b0), "r"(b1));
}
__device__ __forceinline__ float swiglu_act(float gt, float u) {
    gt = fminf(gt, SWIGLU_LIMIT);
    u  = fminf(fmaxf(u, -SWIGLU_LIMIT), SWIGLU_LIMIT);
    float sig = 1.0f / (1.0f + __expf(-SWIGLU_ALPHA * gt));
    return (u + 1.0f) * (gt * sig);
}
__device__ __forceinline__ uint32_t pack2h(float a, float b) {
    __half2 h = __floats2half2_rn(a, b);
    return *reinterpret_cast<uint32_t*>(&h);
}

// ---------------------------------------------------------------------------
// fp32 -> fp16 conversion pre-pass (8 floats -> one 16B store per iter)
// ---------------------------------------------------------------------------
extern "C" __global__ void __launch_bounds__(256)
f2h_kernel(const float4* __restrict__ in, int which, size_t n8) {
    uint4* out = (which == 0) ? (uint4*)g_xh
               : (which == 1) ? (uint4*)g_gwh
               : (which == 2) ? (uint4*)g_uwh
                              : (uint4*)g_dwh;
    size_t i = (size_t)blockIdx.x * blockDim.x + threadIdx.x;
    size_t st = (size_t)gridDim.x * blockDim.x;
    for (; i < n8; i += st) {
        float4 v0 = in[2 * i], v1 = in[2 * i + 1];
        uint4 o;
        o.x = pack2h(v0.x, v0.y);
        o.y = pack2h(v0.z, v0.w);
        o.z = pack2h(v1.x, v1.y);
        o.w = pack2h(v1.z, v1.w);
        out[i] = o;
    }
}

// ---------------------------------------------------------------------------
// Kernel 1: gate+up GEMM (fp16 HMMA) + bias + SwiGLU -> g_act (fp16)
// BM=128, BN=128 (per matrix), BK=32, 3-stage cp.async.
// 8 warps (2 x 4): warp tile 64x32 for each of gate & up.
// smem stage: A 128 rows x 80B | Bg 32 rows x 272B | Bu 32 rows x 272B
// ---------------------------------------------------------------------------
#define BM 128
#define BK 32
#define BN1 128
#define LDA_B 80
#define A_SZ 10240
#define LDB1_B 272
#define B1_SZ 8704
#define STAGE1 (A_SZ + 2 * B1_SZ)      // 27648
#define SMEM1 (3 * STAGE1)             // 82944

extern "C" __global__ void __launch_bounds__(256, 1)
gate_up_h(const int* __restrict__ offs,
          const float* __restrict__ gate_b,
          const float* __restrict__ up_b)
{
    extern __shared__ char smem[];
    const uint32_t sb = smem_u32(smem);
    const int tid = threadIdx.x, wid = tid >> 5, lane = tid & 31;
    const int g = lane >> 2, tg = lane & 3;
    const int warp_m = wid >> 2, warp_n = wid & 3;
    const int m0 = blockIdx.x * BM;
    const int n0 = blockIdx.y * BN1;

    int e = 0;
    while (e < E_NUM - 1 && __ldg(&offs[e]) <= m0) ++e;
    const __half* __restrict__ Wg = g_gwh + (size_t)e * H_DIM * I_DIM;
    const __half* __restrict__ Wu = g_uwh + (size_t)e * H_DIM * I_DIM;

    float accG[4][4][4], accU[4][4][4];
#pragma unroll
    for (int i = 0; i < 4; i++)
#pragma unroll
        for (int j = 0; j < 4; j++)
#pragma unroll
            for (int k = 0; k < 4; k++) { accG[i][j][k] = 0.f; accU[i][j][k] = 0.f; }

    auto load_stage = [&](int kt, int buf) {
        const uint32_t base = sb + (uint32_t)buf * STAGE1;
        const int k0 = kt * BK;
        // A: 128 rows x 64B -> 512 x 16B chunks, 2 per thread
#pragma unroll
        for (int t = 0; t < 2; t++) {
            int idx = tid + t * 256;
            int m = idx >> 2, c = idx & 3;
            cp_async16(base + (uint32_t)(m * LDA_B + c * 16),
                       g_xh + (size_t)(m0 + m) * H_DIM + k0 + c * 8);
        }
        // Bg/Bu: 32 rows x 256B each -> 512 chunks each, 2 per thread per matrix
#pragma unroll
        for (int t = 0; t < 2; t++) {
            int idx = tid + t * 256;
            int k = idx >> 4, c = idx & 15;
            size_t go = (size_t)(k0 + k) * I_DIM + n0 + c * 8;
            uint32_t so = (uint32_t)(k * LDB1_B + c * 16);
            cp_async16(base + A_SZ + so, Wg + go);
            cp_async16(base + A_SZ + B1_SZ + so, Wu + go);
        }
        cp_commit();
    };

    const int KT = H_DIM / BK;    // 64
    load_stage(0, 0);
    load_stage(1, 1);

    // lane-invariant fragment address components
    const int a_row  = warp_m * 64 + (lane & 15);
    const int a_kb   = ((lane >> 4) * 8) * 2;        // byte offset in k
    const int b_krow = lane & 15;
    const int b_nb   = ((lane >> 4) * 8) * 2;        // byte offset in n

    for (int kt = 0; kt < KT; ++kt) {
        if (kt == KT - 1) cp_wait<0>(); else cp_wait<1>();
        __syncthreads();
        if (kt + 2 < KT) load_stage(kt + 2, (kt + 2) % 3);

        const uint32_t base = sb + (uint32_t)(kt % 3) * STAGE1;
        const uint32_t sA = base, sBg = base + A_SZ, sBu = base + A_SZ + B1_SZ;

#pragma unroll
        for (int kk = 0; kk < 2; ++kk) {
            uint32_t a[4][4];
#pragma unroll
            for (int mt = 0; mt < 4; ++mt)
                ldsm4(a[mt], sA + (uint32_t)((a_row + mt * 16) * LDA_B + kk * 32 + a_kb));
            uint32_t bg[2][4], bu[2][4];
#pragma unroll
            for (int h = 0; h < 2; ++h) {
                uint32_t ro = (uint32_t)((kk * 16 + b_krow) * LDB1_B
                                         + (warp_n * 32 + h * 16) * 2 + b_nb);
                ldsm4t(bg[h], sBg + ro);
                ldsm4t(bu[h], sBu + ro);
            }
#pragma unroll
            for (int mt = 0; mt < 4; ++mt)
#pragma unroll
                for (int h = 0; h < 2; ++h) {
                    mma_f16(accG[mt][2 * h],     a[mt], bg[h][0], bg[h][1]);
                    mma_f16(accG[mt][2 * h + 1], a[mt], bg[h][2], bg[h][3]);
                    mma_f16(accU[mt][2 * h],     a[mt], bu[h][0], bu[h][1]);
                    mma_f16(accU[mt][2 * h + 1], a[mt], bu[h][2], bu[h][3]);
                }
        }
        __syncthreads();
    }

    // epilogue: bias + SwiGLU -> g_act (fp16)
    const float* gb = gate_b + (size_t)e * I_DIM;
    const float* ub = up_b   + (size_t)e * I_DIM;
#pragma unroll
    for (int mt = 0; mt < 4; ++mt) {
        int r0 = m0 + warp_m * 64 + mt * 16 + g;
#pragma unroll
        for (int nt = 0; nt < 4; ++nt) {
            int c = n0 + warp_n * 32 + nt * 8 + tg * 2;
            float gb0 = __ldg(&gb[c]), gb1 = __ldg(&gb[c + 1]);
            float ub0 = __ldg(&ub[c]), ub1 = __ldg(&ub[c + 1]);
            float v0x = swiglu_act(accG[mt][nt][0] + gb0, accU[mt][nt][0] + ub0);
            float v0y = swiglu_act(accG[mt][nt][1] + gb1, accU[mt][nt][1] + ub1);
            float v1x = swiglu_act(accG[mt][nt][2] + gb0, accU[mt][nt][2] + ub0);
            float v1y = swiglu_act(accG[mt][nt][3] + gb1, accU[mt][nt][3] + ub1);
            *reinterpret_cast<uint32_t*>(&g_act[(size_t)r0 * I_DIM + c])       = pack2h(v0x, v0y);
            *reinterpret_cast<uint32_t*>(&g_act[(size_t)(r0 + 8) * I_DIM + c]) = pack2h(v1x, v1y);
        }
    }
}

// ---------------------------------------------------------------------------
// Kernel 2: down GEMM (fp16 HMMA) + bias -> out (fp32)
// BM=128, BN=256, BK=32, 3-stage. 8 warps (2 x 4): warp tile 64x64.
// smem stage: A 128 rows x 80B | B 32 rows x 528B
// ---------------------------------------------------------------------------
#define BN2 256
#define LDB2_B 528
#define B2_SZ 16896
#define STAGE2 (A_SZ + B2_SZ)          // 27136
#define SMEM2 (3 * STAGE2)             // 81408

extern "C" __global__ void __launch_bounds__(256, 1)
down_h(const int* __restrict__ offs,
       const float* __restrict__ down_b,
       float* __restrict__ out)
{
    extern __shared__ char smem[];
    const uint32_t sb = smem_u32(smem);
    const int tid = threadIdx.x, wid = tid >> 5, lane = tid & 31;
    const int g = lane >> 2, tg = lane & 3;
    const int warp_m = wid >> 2, warp_n = wid & 3;
    const int m0 = blockIdx.x * BM;
    const int n0 = blockIdx.y * BN2;

    int e = 0;
    while (e < E_NUM - 1 && __ldg(&offs[e]) <= m0) ++e;
    const __half* __restrict__ Wd = g_dwh + (size_t)e * I_DIM * H_DIM;

    float acc[4][8][4];
#pragma unroll
    for (int i = 0; i < 4; i++)
#pragma unroll
        for (int j = 0; j < 8; j++)
#pragma unroll
            for (int k = 0; k < 4; k++) acc[i][j][k] = 0.f;

    auto load_stage = [&](int kt, int buf) {
        const uint32_t base = sb + (uint32_t)buf * STAGE2;
        const int k0 = kt * BK;
#pragma unroll
        for (int t = 0; t < 2; t++) {            // A: 512 chunks
            int idx = tid + t * 256;
            int m = idx >> 2, c = idx & 3;
            cp_async16(base + (uint32_t)(m * LDA_B + c * 16),
                       g_act + (size_t)(m0 + m) * I_DIM + k0 + c * 8);
        }
#pragma unroll
        for (int t = 0; t < 4; t++) {            // B: 32 rows x 512B = 1024 chunks
            int idx = tid + t * 256;
            int k = idx >> 5, c = idx & 31;
            cp_async16(base + A_SZ + (uint32_t)(k * LDB2_B + c * 16),
                       Wd + (size_t)(k0 + k) * H_DIM + n0 + c * 8);
        }
        cp_commit();
    };

    const int KT = I_DIM / BK;    // 128
    load_stage(0, 0);
    load_stage(1, 1);

    const int a_row  = warp_m * 64 + (lane & 15);
    const int a_kb   = ((lane >> 4) * 8) * 2;
    const int b_krow = lane & 15;
    const int b_nb   = ((lane >> 4) * 8) * 2;

    for (int kt = 0; kt < KT; ++kt) {
        if (kt == KT - 1) cp_wait<0>(); else cp_wait<1>();
        __syncthreads();
        if (kt + 2 < KT) load_stage(kt + 2, (kt + 2) % 3);

        const uint32_t base = sb + (uint32_t)(kt % 3) * STAGE2;
        const uint32_t sA = base, sB = base + A_SZ;

#pragma unroll
        for (int kk = 0; kk < 2; ++kk) {
            uint32_t a[4][4];
#pragma unroll
            for (int mt = 0; mt < 4; ++mt)
                ldsm4(a[mt], sA + (uint32_t)((a_row + mt * 16) * LDA_B + kk * 32 + a_kb));
            uint32_t b[4][4];
#pragma unroll
            for (int h = 0; h < 4; ++h)
                ldsm4t(b[h], sB + (uint32_t)((kk * 16 + b_krow) * LDB2_B
                                             + (warp_n * 64 + h * 16) * 2 + b_nb));
#pragma unroll
            for (int mt = 0; mt < 4; ++mt)
#pragma unroll
                for (int h = 0; h < 4; ++h) {
                    mma_f16(acc[mt][2 * h],     a[mt], b[h][0], b[h][1]);
                    mma_f16(acc[mt][2 * h + 1], a[mt], b[h][2], b[h][3]);
                }
        }
        __syncthreads();
    }

    const float* db = down_b + (size_t)e * H_DIM;
#pragma unroll
    for (int mt = 0; mt < 4; ++mt) {
        int r0 = m0 + warp_m * 64 + mt * 16 + g;
#pragma unroll
        for (int nt = 0; nt < 8; ++nt) {
            int c = n0 + warp_n * 64 + nt * 8 + tg * 2;
            float b0 = __ldg(&db[c]), b1 = __ldg(&db[c + 1]);
            float2 v0, v1;
            v0.x = acc[mt][nt][0] + b0;
            v0.y = acc[mt][nt][1] + b1;
            v1.x = acc[mt][nt][2] + b0;
            v1.y = acc[mt][nt][3] + b1;
            *reinterpret_cast<float2*>(&out[(size_t)r0 * H_DIM + c])       = v0;
            *reinterpret_cast<float2*>(&out[(size_t)(r0 + 8) * H_DIM + c]) = v1;
        }
    }
}

// ---------------------------------------------------------------------------
// launch
// ---------------------------------------------------------------------------
extern "C" void kernel_launch(void* const* d_in, const int* in_sizes, int n_in,
                              void* d_out, int out_size)
{
    const float* x      = (const float*)d_in[0];
    const int*   offs   = (const int*)  d_in[1];
    const float* gate_w = (const float*)d_in[2];
    const float* up_w   = (const float*)d_in[3];
    const float* down_w = (const float*)d_in[4];
    const float* gate_b = (const float*)d_in[5];
    const float* up_b   = (const float*)d_in[6];
    const float* down_b = (const float*)d_in[7];
    float* out = (float*)d_out;

    const size_t n8x = (size_t)T_TOK * H_DIM / 8;
    const size_t n8w = (size_t)E_NUM * H_DIM * I_DIM / 8;
    f2h_kernel<<<1024, 256>>>((const float4*)x,      0, n8x);
    f2h_kernel<<<4096, 256>>>((const float4*)gate_w, 1, n8w);
    f2h_kernel<<<4096, 256>>>((const float4*)up_w,   2, n8w);
    f2h_kernel<<<4096, 256>>>((const float4*)down_w, 3, n8w);

    cudaFuncSetAttribute(gate_up_h, cudaFuncAttributeMaxDynamicSharedMemorySize, SMEM1);
    cudaFuncSetAttribute(down_h,    cudaFuncAttributeMaxDynamicSharedMemorySize, SMEM2);

    dim3 g1(T_TOK / BM, I_DIM / BN1);   // (64, 32) — consecutive CTAs share weight cols in L2
    gate_up_h<<<g1, 256, SMEM1>>>(offs, gate_b, up_b);

    dim3 g2(T_TOK / BM, H_DIM / BN2);   // (64, 8)
    down_h<<<g2, 256, SMEM2>>>(offs, down_b, out);
}

// round 8
// speedup vs baseline: 1.7794x; 1.1250x over previous
#include <cuda_runtime.h>
#include <cuda_fp16.h>
#include <cstdint>

#define T_TOK 8192
#define H_DIM 2048
#define I_DIM 4096
#define E_NUM 8
#define SWIGLU_ALPHA 1.702f
#define SWIGLU_LIMIT 7.0f

// Static device scratch (no allocations allowed anywhere).
__device__ __align__(128) __half g_xh [(size_t)T_TOK * H_DIM];
__device__ __align__(128) __half g_gwh[(size_t)E_NUM * H_DIM * I_DIM];
__device__ __align__(128) __half g_uwh[(size_t)E_NUM * H_DIM * I_DIM];
__device__ __align__(128) __half g_dwh[(size_t)E_NUM * I_DIM * H_DIM];
__device__ __align__(128) __half g_act[(size_t)T_TOK * I_DIM];

// ---------------------------------------------------------------------------
// helpers
// ---------------------------------------------------------------------------
__device__ __forceinline__ uint32_t smem_u32(const void* p) {
    uint32_t a;
    asm("{ .reg .u64 t; cvta.to.shared.u64 t, %1; cvt.u32.u64 %0, t; }" : "=r"(a) : "l"(p));
    return a;
}
__device__ __forceinline__ void cp_async16(uint32_t saddr, const void* g) {
    asm volatile("cp.async.cg.shared.global [%0], [%1], 16;\n" :: "r"(saddr), "l"(g));
}
__device__ __forceinline__ void cp_commit() { asm volatile("cp.async.commit_group;\n"); }
template <int N> __device__ __forceinline__ void cp_wait() {
    asm volatile("cp.async.wait_group %0;\n" :: "n"(N));
}
__device__ __forceinline__ void ldsm4(uint32_t r[4], uint32_t addr) {
    asm volatile("ldmatrix.sync.aligned.m8n8.x4.shared.b16 {%0,%1,%2,%3}, [%4];"
                 : "=r"(r[0]), "=r"(r[1]), "=r"(r[2]), "=r"(r[3]) : "r"(addr));
}
__device__ __forceinline__ void ldsm4t(uint32_t r[4], uint32_t addr) {
    asm volatile("ldmatrix.sync.aligned.m8n8.x4.trans.shared.b16 {%0,%1,%2,%3}, [%4];"
                 : "=r"(r[0]), "=r"(r[1]), "=r"(r[2]), "=r"(r[3]) : "r"(addr));
}
__device__ __forceinline__ void mma_f16(float c[4], const uint32_t a[4],
                                        uint32_t b0, uint32_t b1) {
    asm volatile(
        "mma.sync.aligned.m16n8k16.row.col.f32.f16.f16.f32 "
        "{%0,%1,%2,%3}, {%4,%5,%6,%7}, {%8,%9}, {%0,%1,%2,%3};\n"
        : "+f"(c[0]), "+f"(c[1]), "+f"(c[2]), "+f"(c[3])
        : "r"(a[0]), "r"(a[1]), "r"(a[2]), "r"(a[3]), "r"(b0), "r"(b1));
}
__device__ __forceinline__ float swiglu_act(float gt, float u) {
    gt = fminf(gt, SWIGLU_LIMIT);
    u  = fminf(fmaxf(u, -SWIGLU_LIMIT), SWIGLU_LIMIT);
    float sig = 1.0f / (1.0f + __expf(-SWIGLU_ALPHA * gt));
    return (u + 1.0f) * (gt * sig);
}
__device__ __forceinline__ uint32_t pack2h(float a, float b) {
    __half2 h = __floats2half2_rn(a, b);
    return *reinterpret_cast<uint32_t*>(&h);
}

// ---------------------------------------------------------------------------
// fp32 -> fp16 conversion pre-pass
// ---------------------------------------------------------------------------
extern "C" __global__ void __launch_bounds__(256)
f2h_kernel(const float4* __restrict__ in, int which, size_t n8) {
    uint4* out = (which == 0) ? (uint4*)g_xh
               : (which == 1) ? (uint4*)g_gwh
               : (which == 2) ? (uint4*)g_uwh
                              : (uint4*)g_dwh;
    size_t i = (size_t)blockIdx.x * blockDim.x + threadIdx.x;
    size_t st = (size_t)gridDim.x * blockDim.x;
    for (; i < n8; i += st) {
        float4 v0 = in[2 * i], v1 = in[2 * i + 1];
        uint4 o;
        o.x = pack2h(v0.x, v0.y);
        o.y = pack2h(v0.z, v0.w);
        o.z = pack2h(v1.x, v1.y);
        o.w = pack2h(v1.z, v1.w);
        out[i] = o;
    }
}

// ---------------------------------------------------------------------------
// Kernel 1: gate+up GEMM (fp16 HMMA) + bias + SwiGLU -> g_act (fp16)
// BM=128, BN=128 (per matrix), BK=64, 3-stage cp.async.
// 8 warps (2 x 4): warp tile 64x32 for each of gate & up.
// smem stage: A 128 rows x 144B | Bg 64 rows x 272B | Bu 64 rows x 272B
// ---------------------------------------------------------------------------
#define BM 128
#define BK 64
#define BN1 128
#define LDA_B 144
#define A_SZ 18432
#define LDB1_B 272
#define B1_SZ 17408
#define STAGE1 (A_SZ + 2 * B1_SZ)      // 53248
#define SMEM1 (3 * STAGE1)             // 159744

extern "C" __global__ void __launch_bounds__(256, 1)
gate_up_h(const int* __restrict__ offs,
          const float* __restrict__ gate_b,
          const float* __restrict__ up_b)
{
    extern __shared__ char smem[];
    const uint32_t sb = smem_u32(smem);
    const int tid = threadIdx.x, wid = tid >> 5, lane = tid & 31;
    const int g = lane >> 2, tg = lane & 3;
    const int warp_m = wid >> 2, warp_n = wid & 3;
    const int m0 = blockIdx.x * BM;
    const int n0 = blockIdx.y * BN1;

    int e = 0;
    while (e < E_NUM - 1 && __ldg(&offs[e]) <= m0) ++e;
    const __half* __restrict__ Wg = g_gwh + (size_t)e * H_DIM * I_DIM;
    const __half* __restrict__ Wu = g_uwh + (size_t)e * H_DIM * I_DIM;

    float accG[4][4][4], accU[4][4][4];
#pragma unroll
    for (int i = 0; i < 4; i++)
#pragma unroll
        for (int j = 0; j < 4; j++)
#pragma unroll
            for (int k = 0; k < 4; k++) { accG[i][j][k] = 0.f; accU[i][j][k] = 0.f; }

    auto load_stage = [&](int kt, int buf) {
        const uint32_t base = sb + (uint32_t)buf * STAGE1;
        const int k0 = kt * BK;
        // A: 128 rows x 128B -> 1024 x 16B chunks, 4 per thread
#pragma unroll
        for (int t = 0; t < 4; t++) {
            int idx = tid + t * 256;
            int m = idx >> 3, c = idx & 7;
            cp_async16(base + (uint32_t)(m * LDA_B + c * 16),
                       g_xh + (size_t)(m0 + m) * H_DIM + k0 + c * 8);
        }
        // Bg/Bu: 64 rows x 256B each -> 1024 chunks each, 4 per thread per matrix
#pragma unroll
        for (int t = 0; t < 4; t++) {
            int idx = tid + t * 256;
            int k = idx >> 4, c = idx & 15;
            size_t go = (size_t)(k0 + k) * I_DIM + n0 + c * 8;
            uint32_t so = (uint32_t)(k * LDB1_B + c * 16);
            cp_async16(base + A_SZ + so, Wg + go);
            cp_async16(base + A_SZ + B1_SZ + so, Wu + go);
        }
        cp_commit();
    };

    const int KT = H_DIM / BK;    // 32
    load_stage(0, 0);
    load_stage(1, 1);

    // lane-invariant fragment address components
    const int a_row  = warp_m * 64 + (lane & 15);
    const int a_kb   = (lane >> 4) * 16;     // byte offset in k
    const int b_krow = lane & 15;
    const int b_nb   = (lane >> 4) * 16;     // byte offset in n

    uint32_t a[2][4][4], bg[2][2][4], bu[2][2][4];

    for (int kt = 0; kt < KT; ++kt) {
        if (kt == KT - 1) cp_wait<0>(); else cp_wait<1>();
        __syncthreads();
        if (kt + 2 < KT) load_stage(kt + 2, (kt + 2) % 3);

        const uint32_t base = sb + (uint32_t)(kt % 3) * STAGE1;
        const uint32_t sA = base, sBg = base + A_SZ, sBu = base + A_SZ + B1_SZ;

        auto load_frags = [&](int kk, int pb) {
#pragma unroll
            for (int mt = 0; mt < 4; ++mt)
                ldsm4(a[pb][mt], sA + (uint32_t)((a_row + mt * 16) * LDA_B + kk * 32 + a_kb));
#pragma unroll
            for (int h = 0; h < 2; ++h) {
                uint32_t ro = (uint32_t)((kk * 16 + b_krow) * LDB1_B
                                         + (warp_n * 32 + h * 16) * 2 + b_nb);
                ldsm4t(bg[pb][h], sBg + ro);
                ldsm4t(bu[pb][h], sBu + ro);
            }
        };

        load_frags(0, 0);
#pragma unroll
        for (int kk = 0; kk < 4; ++kk) {
            const int cb = kk & 1;
            if (kk < 3) load_frags(kk + 1, cb ^ 1);
#pragma unroll
            for (int mt = 0; mt < 4; ++mt)
#pragma unroll
                for (int h = 0; h < 2; ++h) {
                    mma_f16(accG[mt][2 * h],     a[cb][mt], bg[cb][h][0], bg[cb][h][1]);
                    mma_f16(accG[mt][2 * h + 1], a[cb][mt], bg[cb][h][2], bg[cb][h][3]);
                    mma_f16(accU[mt][2 * h],     a[cb][mt], bu[cb][h][0], bu[cb][h][1]);
                    mma_f16(accU[mt][2 * h + 1], a[cb][mt], bu[cb][h][2], bu[cb][h][3]);
                }
        }
        // no bottom barrier: next iteration's top barrier protects the ring
    }

    // epilogue: bias + SwiGLU -> g_act (fp16)
    const float* gb = gate_b + (size_t)e * I_DIM;
    const float* ub = up_b   + (size_t)e * I_DIM;
#pragma unroll
    for (int mt = 0; mt < 4; ++mt) {
        int r0 = m0 + warp_m * 64 + mt * 16 + g;
#pragma unroll
        for (int nt = 0; nt < 4; ++nt) {
            int c = n0 + warp_n * 32 + nt * 8 + tg * 2;
            float gb0 = __ldg(&gb[c]), gb1 = __ldg(&gb[c + 1]);
            float ub0 = __ldg(&ub[c]), ub1 = __ldg(&ub[c + 1]);
            float v0x = swiglu_act(accG[mt][nt][0] + gb0, accU[mt][nt][0] + ub0);
            float v0y = swiglu_act(accG[mt][nt][1] + gb1, accU[mt][nt][1] + ub1);
            float v1x = swiglu_act(accG[mt][nt][2] + gb0, accU[mt][nt][2] + ub0);
            float v1y = swiglu_act(accG[mt][nt][3] + gb1, accU[mt][nt][3] + ub1);
            *reinterpret_cast<uint32_t*>(&g_act[(size_t)r0 * I_DIM + c])       = pack2h(v0x, v0y);
            *reinterpret_cast<uint32_t*>(&g_act[(size_t)(r0 + 8) * I_DIM + c]) = pack2h(v1x, v1y);
        }
    }
}

// ---------------------------------------------------------------------------
// Kernel 2: down GEMM (fp16 HMMA) + bias -> out (fp32)
// BM=128, BN=256, BK=64, 3-stage. 8 warps (2 x 4): warp tile 64x64.
// smem stage: A 128 rows x 144B | B 64 rows x 528B
// ---------------------------------------------------------------------------
#define BN2 256
#define LDB2_B 528
#define B2_SZ 33792
#define STAGE2 (A_SZ + B2_SZ)          // 52224
#define SMEM2 (3 * STAGE2)             // 156672

extern "C" __global__ void __launch_bounds__(256, 1)
down_h(const int* __restrict__ offs,
       const float* __restrict__ down_b,
       float* __restrict__ out)
{
    extern __shared__ char smem[];
    const uint32_t sb = smem_u32(smem);
    const int tid = threadIdx.x, wid = tid >> 5, lane = tid & 31;
    const int g = lane >> 2, tg = lane & 3;
    const int warp_m = wid >> 2, warp_n = wid & 3;
    const int m0 = blockIdx.x * BM;
    const int n0 = blockIdx.y * BN2;

    int e = 0;
    while (e < E_NUM - 1 && __ldg(&offs[e]) <= m0) ++e;
    const __half* __restrict__ Wd = g_dwh + (size_t)e * I_DIM * H_DIM;

    float acc[4][8][4];
#pragma unroll
    for (int i = 0; i < 4; i++)
#pragma unroll
        for (int j = 0; j < 8; j++)
#pragma unroll
            for (int k = 0; k < 4; k++) acc[i][j][k] = 0.f;

    auto load_stage = [&](int kt, int buf) {
        const uint32_t base = sb + (uint32_t)buf * STAGE2;
        const int k0 = kt * BK;
#pragma unroll
        for (int t = 0; t < 4; t++) {            // A: 1024 chunks
            int idx = tid + t * 256;
            int m = idx >> 3, c = idx & 7;
            cp_async16(base + (uint32_t)(m * LDA_B + c * 16),
                       g_act + (size_t)(m0 + m) * I_DIM + k0 + c * 8);
        }
#pragma unroll
        for (int t = 0; t < 8; t++) {            // B: 64 rows x 512B = 2048 chunks
            int idx = tid + t * 256;
            int k = idx >> 5, c = idx & 31;
            cp_async16(base + A_SZ + (uint32_t)(k * LDB2_B + c * 16),
                       Wd + (size_t)(k0 + k) * H_DIM + n0 + c * 8);
        }
        cp_commit();
    };

    const int KT = I_DIM / BK;    // 64
    load_stage(0, 0);
    load_stage(1, 1);

    const int a_row  = warp_m * 64 + (lane & 15);
    const int a_kb   = (lane >> 4) * 16;
    const int b_krow = lane & 15;
    const int b_nb   = (lane >> 4) * 16;

    uint32_t a[2][4][4], b[2][4][4];

    for (int kt = 0; kt < KT; ++kt) {
        if (kt == KT - 1) cp_wait<0>(); else cp_wait<1>();
        __syncthreads();
        if (kt + 2 < KT) load_stage(kt + 2, (kt + 2) % 3);

        const uint32_t base = sb + (uint32_t)(kt % 3) * STAGE2;
        const uint32_t sA = base, sB = base + A_SZ;

        auto load_frags = [&](int kk, int pb) {
#pragma unroll
            for (int mt = 0; mt < 4; ++mt)
                ldsm4(a[pb][mt], sA + (uint32_t)((a_row + mt * 16) * LDA_B + kk * 32 + a_kb));
#pragma unroll
            for (int h = 0; h < 4; ++h)
                ldsm4t(b[pb][h], sB + (uint32_t)((kk * 16 + b_krow) * LDB2_B
                                                 + (warp_n * 64 + h * 16) * 2 + b_nb));
        };

        load_frags(0, 0);
#pragma unroll
        for (int kk = 0; kk < 4; ++kk) {
            const int cb = kk & 1;
            if (kk < 3) load_frags(kk + 1, cb ^ 1);
#pragma unroll
            for (int mt = 0; mt < 4; ++mt)
#pragma unroll
                for (int h = 0; h < 4; ++h) {
                    mma_f16(acc[mt][2 * h],     a[cb][mt], b[cb][h][0], b[cb][h][1]);
                    mma_f16(acc[mt][2 * h + 1], a[cb][mt], b[cb][h][2], b[cb][h][3]);
                }
        }
        // no bottom barrier: next iteration's top barrier protects the ring
    }

    const float* db = down_b + (size_t)e * H_DIM;
#pragma unroll
    for (int mt = 0; mt < 4; ++mt) {
        int r0 = m0 + warp_m * 64 + mt * 16 + g;
#pragma unroll
        for (int nt = 0; nt < 8; ++nt) {
            int c = n0 + warp_n * 64 + nt * 8 + tg * 2;
            float b0 = __ldg(&db[c]), b1 = __ldg(&db[c + 1]);
            float2 v0, v1;
            v0.x = acc[mt][nt][0] + b0;
            v0.y = acc[mt][nt][1] + b1;
            v1.x = acc[mt][nt][2] + b0;
            v1.y = acc[mt][nt][3] + b1;
            *reinterpret_cast<float2*>(&out[(size_t)r0 * H_DIM + c])       = v0;
            *reinterpret_cast<float2*>(&out[(size_t)(r0 + 8) * H_DIM + c]) = v1;
        }
    }
}

// ---------------------------------------------------------------------------
// launch
// ---------------------------------------------------------------------------
extern "C" void kernel_launch(void* const* d_in, const int* in_sizes, int n_in,
                              void* d_out, int out_size)
{
    const float* x      = (const float*)d_in[0];
    const int*   offs   = (const int*)  d_in[1];
    const float* gate_w = (const float*)d_in[2];
    const float* up_w   = (const float*)d_in[3];
    const float* down_w = (const float*)d_in[4];
    const float* gate_b = (const float*)d_in[5];
    const float* up_b   = (const float*)d_in[6];
    const float* down_b = (const float*)d_in[7];
    float* out = (float*)d_out;

    const size_t n8x = (size_t)T_TOK * H_DIM / 8;
    const size_t n8w = (size_t)E_NUM * H_DIM * I_DIM / 8;
    f2h_kernel<<<1024, 256>>>((const float4*)x,      0, n8x);
    f2h_kernel<<<4096, 256>>>((const float4*)gate_w, 1, n8w);
    f2h_kernel<<<4096, 256>>>((const float4*)up_w,   2, n8w);
    f2h_kernel<<<4096, 256>>>((const float4*)down_w, 3, n8w);

    cudaFuncSetAttribute(gate_up_h, cudaFuncAttributeMaxDynamicSharedMemorySize, SMEM1);
    cudaFuncSetAttribute(down_h,    cudaFuncAttributeMaxDynamicSharedMemorySize, SMEM2);

    dim3 g1(T_TOK / BM, I_DIM / BN1);   // (64, 32)
    gate_up_h<<<g1, 256, SMEM1>>>(offs, gate_b, up_b);

    dim3 g2(T_TOK / BM, H_DIM / BN2);   // (64, 8)
    down_h<<<g2, 256, SMEM2>>>(offs, down_b, out);
}

// round 11
// speedup vs baseline: 1.8584x; 1.0444x over previous
#include <cuda_runtime.h>
#include <cuda_fp16.h>
#include <cstdint>

#define T_TOK 8192
#define H_DIM 2048
#define I_DIM 4096
#define E_NUM 8
#define SWIGLU_ALPHA 1.702f
#define SWIGLU_LIMIT 7.0f

// Static device scratch (no allocations allowed anywhere).
__device__ __align__(128) __half g_xh [(size_t)T_TOK * H_DIM];
__device__ __align__(128) __half g_gwh[(size_t)E_NUM * H_DIM * I_DIM];
__device__ __align__(128) __half g_uwh[(size_t)E_NUM * H_DIM * I_DIM];
__device__ __align__(128) __half g_dwh[(size_t)E_NUM * I_DIM * H_DIM];
__device__ __align__(128) __half g_act[(size_t)T_TOK * I_DIM];

// ---------------------------------------------------------------------------
// helpers
// ---------------------------------------------------------------------------
__device__ __forceinline__ uint32_t smem_u32(const void* p) {
    uint32_t a;
    asm("{ .reg .u64 t; cvta.to.shared.u64 t, %1; cvt.u32.u64 %0, t; }" : "=r"(a) : "l"(p));
    return a;
}
__device__ __forceinline__ void cp_async16(uint32_t saddr, const void* g) {
    asm volatile("cp.async.cg.shared.global [%0], [%1], 16;\n" :: "r"(saddr), "l"(g));
}
__device__ __forceinline__ void cp_commit() { asm volatile("cp.async.commit_group;\n"); }
template <int N> __device__ __forceinline__ void cp_wait() {
    asm volatile("cp.async.wait_group %0;\n" :: "n"(N));
}
__device__ __forceinline__ void ldsm4(uint32_t r[4], uint32_t addr) {
    asm volatile("ldmatrix.sync.aligned.m8n8.x4.shared.b16 {%0,%1,%2,%3}, [%4];"
                 : "=r"(r[0]), "=r"(r[1]), "=r"(r[2]), "=r"(r[3]) : "r"(addr));
}
__device__ __forceinline__ void ldsm4t(uint32_t r[4], uint32_t addr) {
    asm volatile("ldmatrix.sync.aligned.m8n8.x4.trans.shared.b16 {%0,%1,%2,%3}, [%4];"
                 : "=r"(r[0]), "=r"(r[1]), "=r"(r[2]), "=r"(r[3]) : "r"(addr));
}
__device__ __forceinline__ void mma_f16(float c[4], const uint32_t a[4],
                                        uint32_t b0, uint32_t b1) {
    asm volatile(
        "mma.sync.aligned.m16n8k16.row.col.f32.f16.f16.f32 "
        "{%0,%1,%2,%3}, {%4,%5,%6,%7}, {%8,%9}, {%0,%1,%2,%3};\n"
        : "+f"(c[0]), "+f"(c[1]), "+f"(c[2]), "+f"(c[3])
        : "r"(a[0]), "r"(a[1]), "r"(a[2]), "r"(a[3]), "r"(b0), "r"(b1));
}
__device__ __forceinline__ float swiglu_act(float gt, float u) {
    gt = fminf(gt, SWIGLU_LIMIT);
    u  = fminf(fmaxf(u, -SWIGLU_LIMIT), SWIGLU_LIMIT);
    float sig = 1.0f / (1.0f + __expf(-SWIGLU_ALPHA * gt));
    return (u + 1.0f) * (gt * sig);
}
__device__ __forceinline__ uint32_t pack2h(float a, float b) {
    __half2 h = __floats2half2_rn(a, b);
    return *reinterpret_cast<uint32_t*>(&h);
}

// ---------------------------------------------------------------------------
// fp32 -> fp16 conversion pre-pass
// ---------------------------------------------------------------------------
extern "C" __global__ void __launch_bounds__(256)
f2h_kernel(const float4* __restrict__ in, int which, size_t n8) {
    uint4* out = (which == 0) ? (uint4*)g_xh
               : (which == 1) ? (uint4*)g_gwh
               : (which == 2) ? (uint4*)g_uwh
                              : (uint4*)g_dwh;
    size_t i = (size_t)blockIdx.x * blockDim.x + threadIdx.x;
    size_t st = (size_t)gridDim.x * blockDim.x;
    for (; i < n8; i += st) {
        float4 v0 = in[2 * i], v1 = in[2 * i + 1];
        uint4 o;
        o.x = pack2h(v0.x, v0.y);
        o.y = pack2h(v0.z, v0.w);
        o.z = pack2h(v1.x, v1.y);
        o.w = pack2h(v1.z, v1.w);
        out[i] = o;
    }
}

// ---------------------------------------------------------------------------
// Kernel 1: gate+up GEMM (fp16 HMMA) + bias + SwiGLU -> g_act (fp16)
// BM=128, BN=128 (per matrix), BK=64, 4-stage cp.async.
// 8 warps (2 x 4): warp tile 64x32 per matrix.
// ---------------------------------------------------------------------------
#define BM 128
#define BK 64
#define BN1 128
#define LDA_B 144
#define A_SZ 18432
#define LDB1_B 272
#define B1_SZ 17408
#define STAGE1 (A_SZ + 2 * B1_SZ)      // 53248
#define NSTAGE1 4
#define SMEM1 (NSTAGE1 * STAGE1)       // 212992

extern "C" __global__ void __launch_bounds__(256, 1)
gate_up_h(const int* __restrict__ offs,
          const float* __restrict__ gate_b,
          const float* __restrict__ up_b)
{
    extern __shared__ char smem[];
    const uint32_t sb = smem_u32(smem);
    const int tid = threadIdx.x, wid = tid >> 5, lane = tid & 31;
    const int g = lane >> 2, tg = lane & 3;
    const int warp_m = wid >> 2, warp_n = wid & 3;
    const int m0 = blockIdx.x * BM;
    const int n0 = blockIdx.y * BN1;

    int e = 0;
    while (e < E_NUM - 1 && __ldg(&offs[e]) <= m0) ++e;
    const __half* __restrict__ Wg = g_gwh + (size_t)e * H_DIM * I_DIM;
    const __half* __restrict__ Wu = g_uwh + (size_t)e * H_DIM * I_DIM;

    float accG[4][4][4], accU[4][4][4];
#pragma unroll
    for (int i = 0; i < 4; i++)
#pragma unroll
        for (int j = 0; j < 4; j++)
#pragma unroll
            for (int k = 0; k < 4; k++) { accG[i][j][k] = 0.f; accU[i][j][k] = 0.f; }

    auto load_stage = [&](int kt, int buf) {
        const uint32_t base = sb + (uint32_t)buf * STAGE1;
        const int k0 = kt * BK;
#pragma unroll
        for (int t = 0; t < 4; t++) {            // A: 1024 x 16B chunks
            int idx = tid + t * 256;
            int m = idx >> 3, c = idx & 7;
            cp_async16(base + (uint32_t)(m * LDA_B + c * 16),
                       g_xh + (size_t)(m0 + m) * H_DIM + k0 + c * 8);
        }
#pragma unroll
        for (int t = 0; t < 4; t++) {            // Bg/Bu: 1024 chunks each
            int idx = tid + t * 256;
            int k = idx >> 4, c = idx & 15;
            size_t go = (size_t)(k0 + k) * I_DIM + n0 + c * 8;
            uint32_t so = (uint32_t)(k * LDB1_B + c * 16);
            cp_async16(base + A_SZ + so, Wg + go);
            cp_async16(base + A_SZ + B1_SZ + so, Wu + go);
        }
        cp_commit();
    };

    const int KT = H_DIM / BK;    // 32
    load_stage(0, 0);
    load_stage(1, 1);
    load_stage(2, 2);

    const int a_row  = warp_m * 64 + (lane & 15);
    const int a_kb   = (lane >> 4) * 16;
    const int b_krow = lane & 15;
    const int b_nb   = (lane >> 4) * 16;

    uint32_t a[2][4][4], bg[2][2][4], bu[2][2][4];

    for (int kt = 0; kt < KT; ++kt) {
        if (kt < KT - 2)       cp_wait<2>();
        else if (kt == KT - 2) cp_wait<1>();
        else                   cp_wait<0>();
        __syncthreads();
        if (kt + 3 < KT) load_stage(kt + 3, (kt + 3) & 3);

        const uint32_t base = sb + (uint32_t)(kt & 3) * STAGE1;
        const uint32_t sA = base, sBg = base + A_SZ, sBu = base + A_SZ + B1_SZ;

        auto load_frags = [&](int kk, int pb) {
#pragma unroll
            for (int mt = 0; mt < 4; ++mt)
                ldsm4(a[pb][mt], sA + (uint32_t)((a_row + mt * 16) * LDA_B + kk * 32 + a_kb));
#pragma unroll
            for (int h = 0; h < 2; ++h) {
                uint32_t ro = (uint32_t)((kk * 16 + b_krow) * LDB1_B
                                         + (warp_n * 32 + h * 16) * 2 + b_nb);
                ldsm4t(bg[pb][h], sBg + ro);
                ldsm4t(bu[pb][h], sBu + ro);
            }
        };

        load_frags(0, 0);
#pragma unroll
        for (int kk = 0; kk < 4; ++kk) {
            const int cb = kk & 1;
            if (kk < 3) load_frags(kk + 1, cb ^ 1);
#pragma unroll
            for (int mt = 0; mt < 4; ++mt)
#pragma unroll
                for (int h = 0; h < 2; ++h) {
                    mma_f16(accG[mt][2 * h],     a[cb][mt], bg[cb][h][0], bg[cb][h][1]);
                    mma_f16(accG[mt][2 * h + 1], a[cb][mt], bg[cb][h][2], bg[cb][h][3]);
                    mma_f16(accU[mt][2 * h],     a[cb][mt], bu[cb][h][0], bu[cb][h][1]);
                    mma_f16(accU[mt][2 * h + 1], a[cb][mt], bu[cb][h][2], bu[cb][h][3]);
                }
        }
        // ring safety: iteration kt+1's top barrier precedes reuse of this buffer
    }

    // epilogue: bias + SwiGLU -> g_act (fp16)
    const float* gb = gate_b + (size_t)e * I_DIM;
    const float* ub = up_b   + (size_t)e * I_DIM;
#pragma unroll
    for (int mt = 0; mt < 4; ++mt) {
        int r0 = m0 + warp_m * 64 + mt * 16 + g;
#pragma unroll
        for (int nt = 0; nt < 4; ++nt) {
            int c = n0 + warp_n * 32 + nt * 8 + tg * 2;
            float gb0 = __ldg(&gb[c]), gb1 = __ldg(&gb[c + 1]);
            float ub0 = __ldg(&ub[c]), ub1 = __ldg(&ub[c + 1]);
            float v0x = swiglu_act(accG[mt][nt][0] + gb0, accU[mt][nt][0] + ub0);
            float v0y = swiglu_act(accG[mt][nt][1] + gb1, accU[mt][nt][1] + ub1);
            float v1x = swiglu_act(accG[mt][nt][2] + gb0, accU[mt][nt][2] + ub0);
            float v1y = swiglu_act(accG[mt][nt][3] + gb1, accU[mt][nt][3] + ub1);
            *reinterpret_cast<uint32_t*>(&g_act[(size_t)r0 * I_DIM + c])       = pack2h(v0x, v0y);
            *reinterpret_cast<uint32_t*>(&g_act[(size_t)(r0 + 8) * I_DIM + c]) = pack2h(v1x, v1y);
        }
    }
}

// ---------------------------------------------------------------------------
// Kernel 2: down GEMM (fp16 HMMA) + bias -> out (fp32)
// BM=128, BN=128, BK=64, 3-stage, 2 CTAs/SM (grid 1024 -> 6.9 waves).
// 8 warps (2 x 4): warp tile 64x32. Single-buffered fragments (reg budget 128).
// ---------------------------------------------------------------------------
#define BN2 128
#define LDB2_B 272
#define B2_SZ 17408
#define STAGE2 (A_SZ + B2_SZ)          // 35840
#define SMEM2 (3 * STAGE2)             // 107520  (x2 CTAs = 215KB/SM)

extern "C" __global__ void __launch_bounds__(256, 2)
down_h(const int* __restrict__ offs,
       const float* __restrict__ down_b,
       float* __restrict__ out)
{
    extern __shared__ char smem[];
    const uint32_t sb = smem_u32(smem);
    const int tid = threadIdx.x, wid = tid >> 5, lane = tid & 31;
    const int g = lane >> 2, tg = lane & 3;
    const int warp_m = wid >> 2, warp_n = wid & 3;
    const int m0 = blockIdx.x * BM;
    const int n0 = blockIdx.y * BN2;

    int e = 0;
    while (e < E_NUM - 1 && __ldg(&offs[e]) <= m0) ++e;
    const __half* __restrict__ Wd = g_dwh + (size_t)e * I_DIM * H_DIM;

    float acc[4][4][4];
#pragma unroll
    for (int i = 0; i < 4; i++)
#pragma unroll
        for (int j = 0; j < 4; j++)
#pragma unroll
            for (int k = 0; k < 4; k++) acc[i][j][k] = 0.f;

    auto load_stage = [&](int kt, int buf) {
        const uint32_t base = sb + (uint32_t)buf * STAGE2;
        const int k0 = kt * BK;
#pragma unroll
        for (int t = 0; t < 4; t++) {            // A: 1024 chunks
            int idx = tid + t * 256;
            int m = idx >> 3, c = idx & 7;
            cp_async16(base + (uint32_t)(m * LDA_B + c * 16),
                       g_act + (size_t)(m0 + m) * I_DIM + k0 + c * 8);
        }
#pragma unroll
        for (int t = 0; t < 4; t++) {            // B: 64 rows x 256B = 1024 chunks
            int idx = tid + t * 256;
            int k = idx >> 4, c = idx & 15;
            cp_async16(base + A_SZ + (uint32_t)(k * LDB2_B + c * 16),
                       Wd + (size_t)(k0 + k) * H_DIM + n0 + c * 8);
        }
        cp_commit();
    };

    const int KT = I_DIM / BK;    // 64
    load_stage(0, 0);
    load_stage(1, 1);

    const int a_row  = warp_m * 64 + (lane & 15);
    const int a_kb   = (lane >> 4) * 16;
    const int b_krow = lane & 15;
    const int b_nb   = (lane >> 4) * 16;

    for (int kt = 0; kt < KT; ++kt) {
        if (kt == KT - 1) cp_wait<0>(); else cp_wait<1>();
        __syncthreads();
        if (kt + 2 < KT) load_stage(kt + 2, (kt + 2) % 3);

        const uint32_t base = sb + (uint32_t)(kt % 3) * STAGE2;
        const uint32_t sA = base, sB = base + A_SZ;

#pragma unroll
        for (int kk = 0; kk < 4; ++kk) {
            uint32_t a[4][4], b[2][4];
#pragma unroll
            for (int mt = 0; mt < 4; ++mt)
                ldsm4(a[mt], sA + (uint32_t)((a_row + mt * 16) * LDA_B + kk * 32 + a_kb));
#pragma unroll
            for (int h = 0; h < 2; ++h)
                ldsm4t(b[h], sB + (uint32_t)((kk * 16 + b_krow) * LDB2_B
                                             + (warp_n * 32 + h * 16) * 2 + b_nb));
#pragma unroll
            for (int mt = 0; mt < 4; ++mt)
#pragma unroll
                for (int h = 0; h < 2; ++h) {
                    mma_f16(acc[mt][2 * h],     a[mt], b[h][0], b[h][1]);
                    mma_f16(acc[mt][2 * h + 1], a[mt], b[h][2], b[h][3]);
                }
        }
        // ring safety: next iteration's top barrier protects buffer reuse
    }

    const float* db = down_b + (size_t)e * H_DIM;
#pragma unroll
    for (int mt = 0; mt < 4; ++mt) {
        int r0 = m0 + warp_m * 64 + mt * 16 + g;
#pragma unroll
        for (int nt = 0; nt < 4; ++nt) {
            int c = n0 + warp_n * 32 + nt * 8 + tg * 2;
            float b0 = __ldg(&db[c]), b1 = __ldg(&db[c + 1]);
            float2 v0, v1;
            v0.x = acc[mt][nt][0] + b0;
            v0.y = acc[mt][nt][1] + b1;
            v1.x = acc[mt][nt][2] + b0;
            v1.y = acc[mt][nt][3] + b1;
            *reinterpret_cast<float2*>(&out[(size_t)r0 * H_DIM + c])       = v0;
            *reinterpret_cast<float2*>(&out[(size_t)(r0 + 8) * H_DIM + c]) = v1;
        }
    }
}

// ---------------------------------------------------------------------------
// launch
// ---------------------------------------------------------------------------
extern "C" void kernel_launch(void* const* d_in, const int* in_sizes, int n_in,
                              void* d_out, int out_size)
{
    const float* x      = (const float*)d_in[0];
    const int*   offs   = (const int*)  d_in[1];
    const float* gate_w = (const float*)d_in[2];
    const float* up_w   = (const float*)d_in[3];
    const float* down_w = (const float*)d_in[4];
    const float* gate_b = (const float*)d_in[5];
    const float* up_b   = (const float*)d_in[6];
    const float* down_b = (const float*)d_in[7];
    float* out = (float*)d_out;

    const size_t n8x = (size_t)T_TOK * H_DIM / 8;
    const size_t n8w = (size_t)E_NUM * H_DIM * I_DIM / 8;
    f2h_kernel<<<1024, 256>>>((const float4*)x,      0, n8x);
    f2h_kernel<<<4096, 256>>>((const float4*)gate_w, 1, n8w);
    f2h_kernel<<<4096, 256>>>((const float4*)up_w,   2, n8w);
    f2h_kernel<<<4096, 256>>>((const float4*)down_w, 3, n8w);

    cudaFuncSetAttribute(gate_up_h, cudaFuncAttributeMaxDynamicSharedMemorySize, SMEM1);
    cudaFuncSetAttribute(down_h,    cudaFuncAttributeMaxDynamicSharedMemorySize, SMEM2);

    dim3 g1(T_TOK / BM, I_DIM / BN1);   // (64, 32)
    gate_up_h<<<g1, 256, SMEM1>>>(offs, gate_b, up_b);

    dim3 g2(T_TOK / BM, H_DIM / BN2);   // (64, 16) = 1024 CTAs, 2/SM
    down_h<<<g2, 256, SMEM2>>>(offs, down_b, out);
}

// round 12
// speedup vs baseline: 2.0482x; 1.1021x over previous
#include <cuda_runtime.h>
#include <cuda_fp16.h>
#include <cstdint>

#define T_TOK 8192
#define H_DIM 2048
#define I_DIM 4096
#define E_NUM 8
#define SWIGLU_ALPHA 1.702f
#define SWIGLU_LIMIT 7.0f

// Static device scratch (no allocations allowed anywhere).
__device__ __align__(128) __half g_xh [(size_t)T_TOK * H_DIM];
__device__ __align__(128) __half g_gwh[(size_t)E_NUM * H_DIM * I_DIM];
__device__ __align__(128) __half g_uwh[(size_t)E_NUM * H_DIM * I_DIM];
__device__ __align__(128) __half g_dwh[(size_t)E_NUM * I_DIM * H_DIM];
__device__ __align__(128) __half g_act[(size_t)T_TOK * I_DIM];

// ---------------------------------------------------------------------------
// helpers
// ---------------------------------------------------------------------------
__device__ __forceinline__ uint32_t smem_u32(const void* p) {
    uint32_t a;
    asm("{ .reg .u64 t; cvta.to.shared.u64 t, %1; cvt.u32.u64 %0, t; }" : "=r"(a) : "l"(p));
    return a;
}
__device__ __forceinline__ void cp_async16(uint32_t saddr, const void* g) {
    asm volatile("cp.async.cg.shared.global [%0], [%1], 16;\n" :: "r"(saddr), "l"(g));
}
__device__ __forceinline__ void cp_commit() { asm volatile("cp.async.commit_group;\n"); }
template <int N> __device__ __forceinline__ void cp_wait() {
    asm volatile("cp.async.wait_group %0;\n" :: "n"(N));
}
__device__ __forceinline__ void ldsm4(uint32_t r[4], uint32_t addr) {
    asm volatile("ldmatrix.sync.aligned.m8n8.x4.shared.b16 {%0,%1,%2,%3}, [%4];"
                 : "=r"(r[0]), "=r"(r[1]), "=r"(r[2]), "=r"(r[3]) : "r"(addr));
}
__device__ __forceinline__ void ldsm4t(uint32_t r[4], uint32_t addr) {
    asm volatile("ldmatrix.sync.aligned.m8n8.x4.trans.shared.b16 {%0,%1,%2,%3}, [%4];"
                 : "=r"(r[0]), "=r"(r[1]), "=r"(r[2]), "=r"(r[3]) : "r"(addr));
}
__device__ __forceinline__ void mma_f16(float c[4], const uint32_t a[4],
                                        uint32_t b0, uint32_t b1) {
    asm volatile(
        "mma.sync.aligned.m16n8k16.row.col.f32.f16.f16.f32 "
        "{%0,%1,%2,%3}, {%4,%5,%6,%7}, {%8,%9}, {%0,%1,%2,%3};\n"
        : "+f"(c[0]), "+f"(c[1]), "+f"(c[2]), "+f"(c[3])
        : "r"(a[0]), "r"(a[1]), "r"(a[2]), "r"(a[3]), "r"(b0), "r"(b1));
}
__device__ __forceinline__ float swiglu_act(float gt, float u) {
    gt = fminf(gt, SWIGLU_LIMIT);
    u  = fminf(fmaxf(u, -SWIGLU_LIMIT), SWIGLU_LIMIT);
    float sig = 1.0f / (1.0f + __expf(-SWIGLU_ALPHA * gt));
    return (u + 1.0f) * (gt * sig);
}
__device__ __forceinline__ uint32_t pack2h(float a, float b) {
    __half2 h = __floats2half2_rn(a, b);
    return *reinterpret_cast<uint32_t*>(&h);
}

// ---------------------------------------------------------------------------
// fp32 -> fp16 conversion pre-pass
// ---------------------------------------------------------------------------
extern "C" __global__ void __launch_bounds__(256)
f2h_kernel(const float4* __restrict__ in, int which, size_t n8) {
    uint4* out = (which == 0) ? (uint4*)g_xh
               : (which == 1) ? (uint4*)g_gwh
               : (which == 2) ? (uint4*)g_uwh
                              : (uint4*)g_dwh;
    size_t i = (size_t)blockIdx.x * blockDim.x + threadIdx.x;
    size_t st = (size_t)gridDim.x * blockDim.x;
    for (; i < n8; i += st) {
        float4 v0 = in[2 * i], v1 = in[2 * i + 1];
        uint4 o;
        o.x = pack2h(v0.x, v0.y);
        o.y = pack2h(v0.z, v0.w);
        o.z = pack2h(v1.x, v1.y);
        o.w = pack2h(v1.z, v1.w);
        out[i] = o;
    }
}

// ---------------------------------------------------------------------------
// Kernel 1: gate+up GEMM (fp16 HMMA) + bias + SwiGLU -> g_act (fp16)
// BM=128, BN=64 (per matrix), BK=64, 3-stage, 2 CTAs/SM.
// 8 warps (4 x 2): warp tile 32x32 per matrix. Single-buffered fragments.
// smem stage: A 128 x 144B | Bg 64 x 144B | Bu 64 x 144B = 36864 B
// ---------------------------------------------------------------------------
#define BM 128
#define BK 64
#define BN1 64
#define LDA_B 144
#define A_SZ 18432
#define LDB1_B 144
#define B1_SZ 9216
#define STAGE1 (A_SZ + 2 * B1_SZ)      // 36864
#define SMEM1 (3 * STAGE1)             // 110592  (x2 CTAs = 221KB/SM)

extern "C" __global__ void __launch_bounds__(256, 2)
gate_up_h(const int* __restrict__ offs,
          const float* __restrict__ gate_b,
          const float* __restrict__ up_b)
{
    extern __shared__ char smem[];
    const uint32_t sb = smem_u32(smem);
    const int tid = threadIdx.x, wid = tid >> 5, lane = tid & 31;
    const int g = lane >> 2, tg = lane & 3;
    const int warp_m = wid >> 1, warp_n = wid & 1;   // 4 x 2
    const int m0 = blockIdx.x * BM;
    const int n0 = blockIdx.y * BN1;

    int e = 0;
    while (e < E_NUM - 1 && __ldg(&offs[e]) <= m0) ++e;
    const __half* __restrict__ Wg = g_gwh + (size_t)e * H_DIM * I_DIM;
    const __half* __restrict__ Wu = g_uwh + (size_t)e * H_DIM * I_DIM;

    float accG[2][4][4], accU[2][4][4];
#pragma unroll
    for (int i = 0; i < 2; i++)
#pragma unroll
        for (int j = 0; j < 4; j++)
#pragma unroll
            for (int k = 0; k < 4; k++) { accG[i][j][k] = 0.f; accU[i][j][k] = 0.f; }

    auto load_stage = [&](int kt, int buf) {
        const uint32_t base = sb + (uint32_t)buf * STAGE1;
        const int k0 = kt * BK;
#pragma unroll
        for (int t = 0; t < 4; t++) {            // A: 128 rows x 8 chunks = 1024
            int idx = tid + t * 256;
            int m = idx >> 3, c = idx & 7;
            cp_async16(base + (uint32_t)(m * LDA_B + c * 16),
                       g_xh + (size_t)(m0 + m) * H_DIM + k0 + c * 8);
        }
#pragma unroll
        for (int t = 0; t < 2; t++) {            // Bg/Bu: 64 rows x 8 chunks = 512 each
            int idx = tid + t * 256;
            int k = idx >> 3, c = idx & 7;
            size_t go = (size_t)(k0 + k) * I_DIM + n0 + c * 8;
            uint32_t so = (uint32_t)(k * LDB1_B + c * 16);
            cp_async16(base + A_SZ + so, Wg + go);
            cp_async16(base + A_SZ + B1_SZ + so, Wu + go);
        }
        cp_commit();
    };

    const int KT = H_DIM / BK;    // 32
    load_stage(0, 0);
    load_stage(1, 1);

    const int a_row  = warp_m * 32 + (lane & 15);
    const int a_kb   = (lane >> 4) * 16;
    const int b_krow = lane & 15;
    const int b_nb   = (lane >> 4) * 16;

    for (int kt = 0; kt < KT; ++kt) {
        if (kt == KT - 1) cp_wait<0>(); else cp_wait<1>();
        __syncthreads();
        if (kt + 2 < KT) load_stage(kt + 2, (kt + 2) % 3);

        const uint32_t base = sb + (uint32_t)(kt % 3) * STAGE1;
        const uint32_t sA = base, sBg = base + A_SZ, sBu = base + A_SZ + B1_SZ;

#pragma unroll
        for (int kk = 0; kk < 4; ++kk) {
            uint32_t a[2][4], bg[2][4], bu[2][4];
#pragma unroll
            for (int mt = 0; mt < 2; ++mt)
                ldsm4(a[mt], sA + (uint32_t)((a_row + mt * 16) * LDA_B + kk * 32 + a_kb));
#pragma unroll
            for (int h = 0; h < 2; ++h) {
                uint32_t ro = (uint32_t)((kk * 16 + b_krow) * LDB1_B
                                         + (warp_n * 32 + h * 16) * 2 + b_nb);
                ldsm4t(bg[h], sBg + ro);
                ldsm4t(bu[h], sBu + ro);
            }
#pragma unroll
            for (int mt = 0; mt < 2; ++mt)
#pragma unroll
                for (int h = 0; h < 2; ++h) {
                    mma_f16(accG[mt][2 * h],     a[mt], bg[h][0], bg[h][1]);
                    mma_f16(accG[mt][2 * h + 1], a[mt], bg[h][2], bg[h][3]);
                    mma_f16(accU[mt][2 * h],     a[mt], bu[h][0], bu[h][1]);
                    mma_f16(accU[mt][2 * h + 1], a[mt], bu[h][2], bu[h][3]);
                }
        }
        // ring safety: next iteration's top barrier protects buffer reuse
    }

    // epilogue: bias + SwiGLU -> g_act (fp16)
    const float* gb = gate_b + (size_t)e * I_DIM;
    const float* ub = up_b   + (size_t)e * I_DIM;
#pragma unroll
    for (int mt = 0; mt < 2; ++mt) {
        int r0 = m0 + warp_m * 32 + mt * 16 + g;
#pragma unroll
        for (int nt = 0; nt < 4; ++nt) {
            int c = n0 + warp_n * 32 + nt * 8 + tg * 2;
            float gb0 = __ldg(&gb[c]), gb1 = __ldg(&gb[c + 1]);
            float ub0 = __ldg(&ub[c]), ub1 = __ldg(&ub[c + 1]);
            float v0x = swiglu_act(accG[mt][nt][0] + gb0, accU[mt][nt][0] + ub0);
            float v0y = swiglu_act(accG[mt][nt][1] + gb1, accU[mt][nt][1] + ub1);
            float v1x = swiglu_act(accG[mt][nt][2] + gb0, accU[mt][nt][2] + ub0);
            float v1y = swiglu_act(accG[mt][nt][3] + gb1, accU[mt][nt][3] + ub1);
            *reinterpret_cast<uint32_t*>(&g_act[(size_t)r0 * I_DIM + c])       = pack2h(v0x, v0y);
            *reinterpret_cast<uint32_t*>(&g_act[(size_t)(r0 + 8) * I_DIM + c]) = pack2h(v1x, v1y);
        }
    }
}

// ---------------------------------------------------------------------------
// Kernel 2: down GEMM (fp16 HMMA) + bias -> out (fp32)
// BM=128, BN=128, BK=64, 3-stage, 2 CTAs/SM.
// 8 warps (2 x 4): warp tile 64x32. Single-buffered fragments.
// ---------------------------------------------------------------------------
#define BN2 128
#define LDB2_B 272
#define B2_SZ 17408
#define STAGE2 (A_SZ + B2_SZ)          // 35840
#define SMEM2 (3 * STAGE2)             // 107520  (x2 CTAs = 215KB/SM)

extern "C" __global__ void __launch_bounds__(256, 2)
down_h(const int* __restrict__ offs,
       const float* __restrict__ down_b,
       float* __restrict__ out)
{
    extern __shared__ char smem[];
    const uint32_t sb = smem_u32(smem);
    const int tid = threadIdx.x, wid = tid >> 5, lane = tid & 31;
    const int g = lane >> 2, tg = lane & 3;
    const int warp_m = wid >> 2, warp_n = wid & 3;
    const int m0 = blockIdx.x * BM;
    const int n0 = blockIdx.y * BN2;

    int e = 0;
    while (e < E_NUM - 1 && __ldg(&offs[e]) <= m0) ++e;
    const __half* __restrict__ Wd = g_dwh + (size_t)e * I_DIM * H_DIM;

    float acc[4][4][4];
#pragma unroll
    for (int i = 0; i < 4; i++)
#pragma unroll
        for (int j = 0; j < 4; j++)
#pragma unroll
            for (int k = 0; k < 4; k++) acc[i][j][k] = 0.f;

    auto load_stage = [&](int kt, int buf) {
        const uint32_t base = sb + (uint32_t)buf * STAGE2;
        const int k0 = kt * BK;
#pragma unroll
        for (int t = 0; t < 4; t++) {            // A: 1024 chunks
            int idx = tid + t * 256;
            int m = idx >> 3, c = idx & 7;
            cp_async16(base + (uint32_t)(m * LDA_B + c * 16),
                       g_act + (size_t)(m0 + m) * I_DIM + k0 + c * 8);
        }
#pragma unroll
        for (int t = 0; t < 4; t++) {            // B: 64 rows x 16 chunks = 1024
            int idx = tid + t * 256;
            int k = idx >> 4, c = idx & 15;
            cp_async16(base + A_SZ + (uint32_t)(k * LDB2_B + c * 16),
                       Wd + (size_t)(k0 + k) * H_DIM + n0 + c * 8);
        }
        cp_commit();
    };

    const int KT = I_DIM / BK;    // 64
    load_stage(0, 0);
    load_stage(1, 1);

    const int a_row  = warp_m * 64 + (lane & 15);
    const int a_kb   = (lane >> 4) * 16;
    const int b_krow = lane & 15;
    const int b_nb   = (lane >> 4) * 16;

    for (int kt = 0; kt < KT; ++kt) {
        if (kt == KT - 1) cp_wait<0>(); else cp_wait<1>();
        __syncthreads();
        if (kt + 2 < KT) load_stage(kt + 2, (kt + 2) % 3);

        const uint32_t base = sb + (uint32_t)(kt % 3) * STAGE2;
        const uint32_t sA = base, sB = base + A_SZ;

#pragma unroll
        for (int kk = 0; kk < 4; ++kk) {
            uint32_t a[4][4], b[2][4];
#pragma unroll
            for (int mt = 0; mt < 4; ++mt)
                ldsm4(a[mt], sA + (uint32_t)((a_row + mt * 16) * LDA_B + kk * 32 + a_kb));
#pragma unroll
            for (int h = 0; h < 2; ++h)
                ldsm4t(b[h], sB + (uint32_t)((kk * 16 + b_krow) * LDB2_B
                                             + (warp_n * 32 + h * 16) * 2 + b_nb));
#pragma unroll
            for (int mt = 0; mt < 4; ++mt)
#pragma unroll
                for (int h = 0; h < 2; ++h) {
                    mma_f16(acc[mt][2 * h],     a[mt], b[h][0], b[h][1]);
                    mma_f16(acc[mt][2 * h + 1], a[mt], b[h][2], b[h][3]);
                }
        }
        // ring safety: next iteration's top barrier protects buffer reuse
    }

    const float* db = down_b + (size_t)e * H_DIM;
#pragma unroll
    for (int mt = 0; mt < 4; ++mt) {
        int r0 = m0 + warp_m * 64 + mt * 16 + g;
#pragma unroll
        for (int nt = 0; nt < 4; ++nt) {
            int c = n0 + warp_n * 32 + nt * 8 + tg * 2;
            float b0 = __ldg(&db[c]), b1 = __ldg(&db[c + 1]);
            float2 v0, v1;
            v0.x = acc[mt][nt][0] + b0;
            v0.y = acc[mt][nt][1] + b1;
            v1.x = acc[mt][nt][2] + b0;
            v1.y = acc[mt][nt][3] + b1;
            *reinterpret_cast<float2*>(&out[(size_t)r0 * H_DIM + c])       = v0;
            *reinterpret_cast<float2*>(&out[(size_t)(r0 + 8) * H_DIM + c]) = v1;
        }
    }
}

// ---------------------------------------------------------------------------
// launch
// ---------------------------------------------------------------------------
extern "C" void kernel_launch(void* const* d_in, const int* in_sizes, int n_in,
                              void* d_out, int out_size)
{
    const float* x      = (const float*)d_in[0];
    const int*   offs   = (const int*)  d_in[1];
    const float* gate_w = (const float*)d_in[2];
    const float* up_w   = (const float*)d_in[3];
    const float* down_w = (const float*)d_in[4];
    const float* gate_b = (const float*)d_in[5];
    const float* up_b   = (const float*)d_in[6];
    const float* down_b = (const float*)d_in[7];
    float* out = (float*)d_out;

    const size_t n8x = (size_t)T_TOK * H_DIM / 8;
    const size_t n8w = (size_t)E_NUM * H_DIM * I_DIM / 8;
    f2h_kernel<<<1024, 256>>>((const float4*)x,      0, n8x);
    f2h_kernel<<<4096, 256>>>((const float4*)gate_w, 1, n8w);
    f2h_kernel<<<4096, 256>>>((const float4*)up_w,   2, n8w);
    f2h_kernel<<<4096, 256>>>((const float4*)down_w, 3, n8w);

    cudaFuncSetAttribute(gate_up_h, cudaFuncAttributeMaxDynamicSharedMemorySize, SMEM1);
    cudaFuncSetAttribute(down_h,    cudaFuncAttributeMaxDynamicSharedMemorySize, SMEM2);

    dim3 g1(T_TOK / BM, I_DIM / BN1);   // (64, 64) = 4096 CTAs, 2/SM
    gate_up_h<<<g1, 256, SMEM1>>>(offs, gate_b, up_b);

    dim3 g2(T_TOK / BM, H_DIM / BN2);   // (64, 16) = 1024 CTAs, 2/SM
    down_h<<<g2, 256, SMEM2>>>(offs, down_b, out);
}

// round 13
// speedup vs baseline: 2.1038x; 1.0271x over previous
#include <cuda_runtime.h>
#include <cuda_fp16.h>
#include <cstdint>

#define T_TOK 8192
#define H_DIM 2048
#define I_DIM 4096
#define E_NUM 8
#define SWIGLU_ALPHA 1.702f
#define SWIGLU_LIMIT 7.0f

// Static device scratch (no allocations allowed anywhere).
__device__ __align__(128) __half g_xh [(size_t)T_TOK * H_DIM];
__device__ __align__(128) __half g_gwh[(size_t)E_NUM * H_DIM * I_DIM];
__device__ __align__(128) __half g_uwh[(size_t)E_NUM * H_DIM * I_DIM];
__device__ __align__(128) __half g_dwh[(size_t)E_NUM * I_DIM * H_DIM];
__device__ __align__(128) __half g_act[(size_t)T_TOK * I_DIM];

// ---------------------------------------------------------------------------
// helpers
// ---------------------------------------------------------------------------
__device__ __forceinline__ uint32_t smem_u32(const void* p) {
    uint32_t a;
    asm("{ .reg .u64 t; cvta.to.shared.u64 t, %1; cvt.u32.u64 %0, t; }" : "=r"(a) : "l"(p));
    return a;
}
__device__ __forceinline__ void cp_async16(uint32_t saddr, const void* g) {
    asm volatile("cp.async.cg.shared.global [%0], [%1], 16;\n" :: "r"(saddr), "l"(g));
}
__device__ __forceinline__ void cp_commit() { asm volatile("cp.async.commit_group;\n"); }
template <int N> __device__ __forceinline__ void cp_wait() {
    asm volatile("cp.async.wait_group %0;\n" :: "n"(N));
}
__device__ __forceinline__ void ldsm4(uint32_t r[4], uint32_t addr) {
    asm volatile("ldmatrix.sync.aligned.m8n8.x4.shared.b16 {%0,%1,%2,%3}, [%4];"
                 : "=r"(r[0]), "=r"(r[1]), "=r"(r[2]), "=r"(r[3]) : "r"(addr));
}
__device__ __forceinline__ void ldsm4t(uint32_t r[4], uint32_t addr) {
    asm volatile("ldmatrix.sync.aligned.m8n8.x4.trans.shared.b16 {%0,%1,%2,%3}, [%4];"
                 : "=r"(r[0]), "=r"(r[1]), "=r"(r[2]), "=r"(r[3]) : "r"(addr));
}
__device__ __forceinline__ void mma_f16(float c[4], const uint32_t a[4],
                                        uint32_t b0, uint32_t b1) {
    asm volatile(
        "mma.sync.aligned.m16n8k16.row.col.f32.f16.f16.f32 "
        "{%0,%1,%2,%3}, {%4,%5,%6,%7}, {%8,%9}, {%0,%1,%2,%3};\n"
        : "+f"(c[0]), "+f"(c[1]), "+f"(c[2]), "+f"(c[3])
        : "r"(a[0]), "r"(a[1]), "r"(a[2]), "r"(a[3]), "r"(b0), "r"(b1));
}
__device__ __forceinline__ float swiglu_act(float gt, float u) {
    gt = fminf(gt, SWIGLU_LIMIT);
    u  = fminf(fmaxf(u, -SWIGLU_LIMIT), SWIGLU_LIMIT);
    float sig = 1.0f / (1.0f + __expf(-SWIGLU_ALPHA * gt));
    return (u + 1.0f) * (gt * sig);
}
__device__ __forceinline__ uint32_t pack2h(float a, float b) {
    __half2 h = __floats2half2_rn(a, b);
    return *reinterpret_cast<uint32_t*>(&h);
}
__device__ __forceinline__ void conv8(const float4* __restrict__ in, uint4* __restrict__ out,
                                      size_t i) {
    float4 v0 = in[2 * i], v1 = in[2 * i + 1];
    uint4 o;
    o.x = pack2h(v0.x, v0.y);
    o.y = pack2h(v0.z, v0.w);
    o.z = pack2h(v1.x, v1.y);
    o.w = pack2h(v1.z, v1.w);
    out[i] = o;
}

// ---------------------------------------------------------------------------
// merged fp32->fp16 conversion pre-pass: x, gate_w, up_w in ONE launch
// ---------------------------------------------------------------------------
extern "C" __global__ void __launch_bounds__(256)
conv3_kernel(const float4* __restrict__ x,
             const float4* __restrict__ gw,
             const float4* __restrict__ uw) {
    const size_t n8x = (size_t)T_TOK * H_DIM / 8;
    const size_t n8w = (size_t)E_NUM * H_DIM * I_DIM / 8;
    size_t tid0 = (size_t)blockIdx.x * blockDim.x + threadIdx.x;
    size_t st   = (size_t)gridDim.x * blockDim.x;
    for (size_t i = tid0; i < n8x; i += st) conv8(x,  (uint4*)g_xh,  i);
    for (size_t i = tid0; i < n8w; i += st) conv8(gw, (uint4*)g_gwh, i);
    for (size_t i = tid0; i < n8w; i += st) conv8(uw, (uint4*)g_uwh, i);
}

// ---------------------------------------------------------------------------
// Kernel 1: gate+up GEMM (fp16 HMMA) + bias + SwiGLU -> g_act (fp16)
//           PLUS embedded down_w fp32->fp16 conversion CTAs.
// 1D grid of 4608 CTAs: bids with bid%9==8 (512 CTAs) convert down_w
// (pure DRAM work riding on bandwidth the GEMM CTAs leave idle);
// the other 4096 CTAs run the GEMM: gemm_id = bid - bid/9,
// m-tile = gemm_id % 64, n-tile = gemm_id / 64 (same layout as before).
// GEMM: BM=128, BN=64 (per matrix), BK=64, 3-stage, 2 CTAs/SM.
// 8 warps (4 x 2): warp tile 32x32 per matrix. Single-buffered fragments.
// ---------------------------------------------------------------------------
#define BM 128
#define BK 64
#define BN1 64
#define LDA_B 144
#define A_SZ 18432
#define LDB1_B 144
#define B1_SZ 9216
#define STAGE1 (A_SZ + 2 * B1_SZ)      // 36864
#define SMEM1 (3 * STAGE1)             // 110592  (x2 CTAs = 221KB/SM)
#define GU_CONV_CTAS 512
#define GU_GRID (4096 + GU_CONV_CTAS)  // 4608 = 9 * 512

extern "C" __global__ void __launch_bounds__(256, 2)
gate_up_h(const int* __restrict__ offs,
          const float* __restrict__ gate_b,
          const float* __restrict__ up_b,
          const float4* __restrict__ down_w32)
{
    const int bid = blockIdx.x;
    const int tid = threadIdx.x;

    if (bid % 9 == 8) {
        // --- embedded down_w converter CTA ---
        const size_t n8w = (size_t)E_NUM * I_DIM * H_DIM / 8;
        size_t i  = (size_t)(bid / 9) * blockDim.x + tid;
        size_t st = (size_t)GU_CONV_CTAS * blockDim.x;
        for (; i < n8w; i += st) conv8(down_w32, (uint4*)g_dwh, i);
        return;
    }
    const int gemm_id = bid - bid / 9;
    const int m0 = (gemm_id & 63) * BM;
    const int n0 = (gemm_id >> 6) * BN1;

    extern __shared__ char smem[];
    const uint32_t sb = smem_u32(smem);
    const int wid = tid >> 5, lane = tid & 31;
    const int g = lane >> 2, tg = lane & 3;
    const int warp_m = wid >> 1, warp_n = wid & 1;   // 4 x 2

    int e = 0;
    while (e < E_NUM - 1 && __ldg(&offs[e]) <= m0) ++e;
    const __half* __restrict__ Wg = g_gwh + (size_t)e * H_DIM * I_DIM;
    const __half* __restrict__ Wu = g_uwh + (size_t)e * H_DIM * I_DIM;

    float accG[2][4][4], accU[2][4][4];
#pragma unroll
    for (int i = 0; i < 2; i++)
#pragma unroll
        for (int j = 0; j < 4; j++)
#pragma unroll
            for (int k = 0; k < 4; k++) { accG[i][j][k] = 0.f; accU[i][j][k] = 0.f; }

    auto load_stage = [&](int kt, int buf) {
        const uint32_t base = sb + (uint32_t)buf * STAGE1;
        const int k0 = kt * BK;
#pragma unroll
        for (int t = 0; t < 4; t++) {            // A: 128 rows x 8 chunks = 1024
            int idx = tid + t * 256;
            int m = idx >> 3, c = idx & 7;
            cp_async16(base + (uint32_t)(m * LDA_B + c * 16),
                       g_xh + (size_t)(m0 + m) * H_DIM + k0 + c * 8);
        }
#pragma unroll
        for (int t = 0; t < 2; t++) {            // Bg/Bu: 64 rows x 8 chunks = 512 each
            int idx = tid + t * 256;
            int k = idx >> 3, c = idx & 7;
            size_t go = (size_t)(k0 + k) * I_DIM + n0 + c * 8;
            uint32_t so = (uint32_t)(k * LDB1_B + c * 16);
            cp_async16(base + A_SZ + so, Wg + go);
            cp_async16(base + A_SZ + B1_SZ + so, Wu + go);
        }
        cp_commit();
    };

    const int KT = H_DIM / BK;    // 32
    load_stage(0, 0);
    load_stage(1, 1);

    const int a_row  = warp_m * 32 + (lane & 15);
    const int a_kb   = (lane >> 4) * 16;
    const int b_krow = lane & 15;
    const int b_nb   = (lane >> 4) * 16;

    for (int kt = 0; kt < KT; ++kt) {
        if (kt == KT - 1) cp_wait<0>(); else cp_wait<1>();
        __syncthreads();
        if (kt + 2 < KT) load_stage(kt + 2, (kt + 2) % 3);

        const uint32_t base = sb + (uint32_t)(kt % 3) * STAGE1;
        const uint32_t sA = base, sBg = base + A_SZ, sBu = base + A_SZ + B1_SZ;

#pragma unroll
        for (int kk = 0; kk < 4; ++kk) {
            uint32_t a[2][4], bg[2][4], bu[2][4];
#pragma unroll
            for (int mt = 0; mt < 2; ++mt)
                ldsm4(a[mt], sA + (uint32_t)((a_row + mt * 16) * LDA_B + kk * 32 + a_kb));
#pragma unroll
            for (int h = 0; h < 2; ++h) {
                uint32_t ro = (uint32_t)((kk * 16 + b_krow) * LDB1_B
                                         + (warp_n * 32 + h * 16) * 2 + b_nb);
                ldsm4t(bg[h], sBg + ro);
                ldsm4t(bu[h], sBu + ro);
            }
#pragma unroll
            for (int mt = 0; mt < 2; ++mt)
#pragma unroll
                for (int h = 0; h < 2; ++h) {
                    mma_f16(accG[mt][2 * h],     a[mt], bg[h][0], bg[h][1]);
                    mma_f16(accG[mt][2 * h + 1], a[mt], bg[h][2], bg[h][3]);
                    mma_f16(accU[mt][2 * h],     a[mt], bu[h][0], bu[h][1]);
                    mma_f16(accU[mt][2 * h + 1], a[mt], bu[h][2], bu[h][3]);
                }
        }
        // ring safety: next iteration's top barrier protects buffer reuse
    }

    // epilogue: bias + SwiGLU -> g_act (fp16)
    const float* gb = gate_b + (size_t)e * I_DIM;
    const float* ub = up_b   + (size_t)e * I_DIM;
#pragma unroll
    for (int mt = 0; mt < 2; ++mt) {
        int r0 = m0 + warp_m * 32 + mt * 16 + g;
#pragma unroll
        for (int nt = 0; nt < 4; ++nt) {
            int c = n0 + warp_n * 32 + nt * 8 + tg * 2;
            float gb0 = __ldg(&gb[c]), gb1 = __ldg(&gb[c + 1]);
            float ub0 = __ldg(&ub[c]), ub1 = __ldg(&ub[c + 1]);
            float v0x = swiglu_act(accG[mt][nt][0] + gb0, accU[mt][nt][0] + ub0);
            float v0y = swiglu_act(accG[mt][nt][1] + gb1, accU[mt][nt][1] + ub1);
            float v1x = swiglu_act(accG[mt][nt][2] + gb0, accU[mt][nt][2] + ub0);
            float v1y = swiglu_act(accG[mt][nt][3] + gb1, accU[mt][nt][3] + ub1);
            *reinterpret_cast<uint32_t*>(&g_act[(size_t)r0 * I_DIM + c])       = pack2h(v0x, v0y);
            *reinterpret_cast<uint32_t*>(&g_act[(size_t)(r0 + 8) * I_DIM + c]) = pack2h(v1x, v1y);
        }
    }
}

// ---------------------------------------------------------------------------
// Kernel 2: down GEMM (fp16 HMMA) + bias -> out (fp32)
// BM=128, BN=128, BK=64, 3-stage, 2 CTAs/SM.
// 8 warps (2 x 4): warp tile 64x32. Single-buffered fragments.
// ---------------------------------------------------------------------------
#define BN2 128
#define LDB2_B 272
#define B2_SZ 17408
#define STAGE2 (A_SZ + B2_SZ)          // 35840
#define SMEM2 (3 * STAGE2)             // 107520  (x2 CTAs = 215KB/SM)

extern "C" __global__ void __launch_bounds__(256, 2)
down_h(const int* __restrict__ offs,
       const float* __restrict__ down_b,
       float* __restrict__ out)
{
    extern __shared__ char smem[];
    const uint32_t sb = smem_u32(smem);
    const int tid = threadIdx.x, wid = tid >> 5, lane = tid & 31;
    const int g = lane >> 2, tg = lane & 3;
    const int warp_m = wid >> 2, warp_n = wid & 3;
    const int m0 = blockIdx.x * BM;
    const int n0 = blockIdx.y * BN2;

    int e = 0;
    while (e < E_NUM - 1 && __ldg(&offs[e]) <= m0) ++e;
    const __half* __restrict__ Wd = g_dwh + (size_t)e * I_DIM * H_DIM;

    float acc[4][4][4];
#pragma unroll
    for (int i = 0; i < 4; i++)
#pragma unroll
        for (int j = 0; j < 4; j++)
#pragma unroll
            for (int k = 0; k < 4; k++) acc[i][j][k] = 0.f;

    auto load_stage = [&](int kt, int buf) {
        const uint32_t base = sb + (uint32_t)buf * STAGE2;
        const int k0 = kt * BK;
#pragma unroll
        for (int t = 0; t < 4; t++) {            // A: 1024 chunks
            int idx = tid + t * 256;
            int m = idx >> 3, c = idx & 7;
            cp_async16(base + (uint32_t)(m * LDA_B + c * 16),
                       g_act + (size_t)(m0 + m) * I_DIM + k0 + c * 8);
        }
#pragma unroll
        for (int t = 0; t < 4; t++) {            // B: 64 rows x 16 chunks = 1024
            int idx = tid + t * 256;
            int k = idx >> 4, c = idx & 15;
            cp_async16(base + A_SZ + (uint32_t)(k * LDB2_B + c * 16),
                       Wd + (size_t)(k0 + k) * H_DIM + n0 + c * 8);
        }
        cp_commit();
    };

    const int KT = I_DIM / BK;    // 64
    load_stage(0, 0);
    load_stage(1, 1);

    const int a_row  = warp_m * 64 + (lane & 15);
    const int a_kb   = (lane >> 4) * 16;
    const int b_krow = lane & 15;
    const int b_nb   = (lane >> 4) * 16;

    for (int kt = 0; kt < KT; ++kt) {
        if (kt == KT - 1) cp_wait<0>(); else cp_wait<1>();
        __syncthreads();
        if (kt + 2 < KT) load_stage(kt + 2, (kt + 2) % 3);

        const uint32_t base = sb + (uint32_t)(kt % 3) * STAGE2;
        const uint32_t sA = base, sB = base + A_SZ;

#pragma unroll
        for (int kk = 0; kk < 4; ++kk) {
            uint32_t a[4][4], b[2][4];
#pragma unroll
            for (int mt = 0; mt < 4; ++mt)
                ldsm4(a[mt], sA + (uint32_t)((a_row + mt * 16) * LDA_B + kk * 32 + a_kb));
#pragma unroll
            for (int h = 0; h < 2; ++h)
                ldsm4t(b[h], sB + (uint32_t)((kk * 16 + b_krow) * LDB2_B
                                             + (warp_n * 32 + h * 16) * 2 + b_nb));
#pragma unroll
            for (int mt = 0; mt < 4; ++mt)
#pragma unroll
                for (int h = 0; h < 2; ++h) {
                    mma_f16(acc[mt][2 * h],     a[mt], b[h][0], b[h][1]);
                    mma_f16(acc[mt][2 * h + 1], a[mt], b[h][2], b[h][3]);
                }
        }
        // ring safety: next iteration's top barrier protects buffer reuse
    }

    const float* db = down_b + (size_t)e * H_DIM;
#pragma unroll
    for (int mt = 0; mt < 4; ++mt) {
        int r0 = m0 + warp_m * 64 + mt * 16 + g;
#pragma unroll
        for (int nt = 0; nt < 4; ++nt) {
            int c = n0 + warp_n * 32 + nt * 8 + tg * 2;
            float b0 = __ldg(&db[c]), b1 = __ldg(&db[c + 1]);
            float2 v0, v1;
            v0.x = acc[mt][nt][0] + b0;
            v0.y = acc[mt][nt][1] + b1;
            v1.x = acc[mt][nt][2] + b0;
            v1.y = acc[mt][nt][3] + b1;
            *reinterpret_cast<float2*>(&out[(size_t)r0 * H_DIM + c])       = v0;
            *reinterpret_cast<float2*>(&out[(size_t)(r0 + 8) * H_DIM + c]) = v1;
        }
    }
}

// ---------------------------------------------------------------------------
// launch
// ---------------------------------------------------------------------------
extern "C" void kernel_launch(void* const* d_in, const int* in_sizes, int n_in,
                              void* d_out, int out_size)
{
    const float* x      = (const float*)d_in[0];
    const int*   offs   = (const int*)  d_in[1];
    const float* gate_w = (const float*)d_in[2];
    const float* up_w   = (const float*)d_in[3];
    const float* down_w = (const float*)d_in[4];
    const float* gate_b = (const float*)d_in[5];
    const float* up_b   = (const float*)d_in[6];
    const float* down_b = (const float*)d_in[7];
    float* out = (float*)d_out;

    // merged conversion of x + gate_w + up_w (down_w converts inside gate_up_h)
    conv3_kernel<<<6144, 256>>>((const float4*)x, (const float4*)gate_w,
                                (const float4*)up_w);

    cudaFuncSetAttribute(gate_up_h, cudaFuncAttributeMaxDynamicSharedMemorySize, SMEM1);
    cudaFuncSetAttribute(down_h,    cudaFuncAttributeMaxDynamicSharedMemorySize, SMEM2);

    // 4096 GEMM CTAs + 512 down_w-converter CTAs interleaved (every 9th bid)
    gate_up_h<<<GU_GRID, 256, SMEM1>>>(offs, gate_b, up_b, (const float4*)down_w);

    dim3 g2(T_TOK / BM, H_DIM / BN2);   // (64, 16) = 1024 CTAs, 2/SM
    down_h<<<g2, 256, SMEM2>>>(offs, down_b, out);
}